// round 1
// baseline (speedup 1.0000x reference)
#include <cuda_runtime.h>
#include <cfloat>
#include <math.h>

// Problem constants
#define BB 4
#define TT 2048
#define EE 1024
#define HH 16
#define DH 64
#define MROWS (BB*TT)        // 8192

// ---------------- scratch (device globals; no allocation allowed) ----------
__device__ float g_h   [(size_t)MROWS*EE];       // LN output (reused for LN1 and LN2)
__device__ float g_wqkv[(size_t)EE*3072];        // packed QKV weights [E, 3*E]
__device__ float g_q   [(size_t)BB*HH*TT*DH];
__device__ float g_k   [(size_t)BB*HH*TT*DH];
__device__ float g_v   [(size_t)BB*HH*TT*DH];
__device__ float g_att [(size_t)MROWS*EE];       // attention out, [B,T,E] (heads concat)
__device__ float g_x1  [(size_t)MROWS*EE];       // x + attn proj
__device__ float g_ffh [(size_t)MROWS*4096];     // relu(h2@W1+b1)

// ---------------- LayerNorm: one block per row of 1024 ---------------------
__global__ void __launch_bounds__(256) ln_kernel(
    const float* __restrict__ x, const float* __restrict__ g,
    const float* __restrict__ b, float* __restrict__ out)
{
    int row = blockIdx.x;
    int tid = threadIdx.x;
    const float4* x4 = (const float4*)(x + (size_t)row * EE);
    float4 xv = x4[tid];
    float s  = xv.x + xv.y + xv.z + xv.w;
    float s2 = xv.x*xv.x + xv.y*xv.y + xv.z*xv.z + xv.w*xv.w;
    #pragma unroll
    for (int o = 16; o > 0; o >>= 1) {
        s  += __shfl_xor_sync(0xffffffffu, s,  o);
        s2 += __shfl_xor_sync(0xffffffffu, s2, o);
    }
    __shared__ float rs[8], rs2[8];
    int w = tid >> 5;
    if ((tid & 31) == 0) { rs[w] = s; rs2[w] = s2; }
    __syncthreads();
    s = 0.f; s2 = 0.f;
    #pragma unroll
    for (int i = 0; i < 8; i++) { s += rs[i]; s2 += rs2[i]; }
    float mean = s * (1.0f/1024.0f);
    float var  = s2 * (1.0f/1024.0f) - mean*mean;
    float inv  = rsqrtf(var + 1e-5f);
    float4 gv = ((const float4*)g)[tid];
    float4 bv = ((const float4*)b)[tid];
    float4 ov;
    ov.x = (xv.x - mean) * inv * gv.x + bv.x;
    ov.y = (xv.y - mean) * inv * gv.y + bv.y;
    ov.z = (xv.z - mean) * inv * gv.z + bv.z;
    ov.w = (xv.w - mean) * inv * gv.w + bv.w;
    ((float4*)(out + (size_t)row * EE))[tid] = ov;
}

// ---------------- pack Wq/Wk/Wv [H,E,DH] -> [E, 3*1024] row-major ----------
__global__ void pack_qkv_kernel(const float* __restrict__ Wq,
                                const float* __restrict__ Wk,
                                const float* __restrict__ Wv,
                                float* __restrict__ Wpk)
{
    int i = blockIdx.x * 256 + threadIdx.x;   // 3*1024*1024 total
    int e  = i / 3072;
    int n  = i % 3072;
    int t  = n >> 10;
    int nn = n & 1023;
    int h  = nn >> 6;
    int d  = nn & 63;
    const float* W = (t == 0) ? Wq : (t == 1) ? Wk : Wv;
    Wpk[i] = W[(size_t)h * EE * DH + (size_t)e * DH + d];
}

// ---------------- SGEMM: C = A[MxK] * B[KxN], 128x128 tile, 8x8/thread ----
enum { EPI_QKV = 0, EPI_BIAS_RESID = 1, EPI_BIAS_RELU = 2 };

template<int EPI>
__global__ void __launch_bounds__(256) sgemm_kernel(
    const float* __restrict__ A, const float* __restrict__ Bm,
    float* __restrict__ C, int M, int N, int K,
    const float* __restrict__ bias, const float* __restrict__ resid,
    float* __restrict__ oq, float* __restrict__ ok, float* __restrict__ ov)
{
    __shared__ float As[8][132];   // transposed A tile: As[k][m]
    __shared__ float Bs[8][132];   // natural B tile:    Bs[k][n]
    int tid = threadIdx.x;
    int tx = tid & 15, ty = tid >> 4;
    int m0 = blockIdx.y * 128, n0 = blockIdx.x * 128;

    float acc[8][8];
    #pragma unroll
    for (int i = 0; i < 8; i++)
        #pragma unroll
        for (int j = 0; j < 8; j++) acc[i][j] = 0.f;

    int arow = tid >> 1, ac4 = (tid & 1) * 4;     // 128 rows x 8 cols (2xfloat4)
    int brow = tid >> 5, bc4 = (tid & 31) * 4;    // 8 rows x 128 cols
    const float* Aptr = A + (size_t)(m0 + arow) * K + ac4;
    const float* Bptr = Bm + (size_t)brow * N + n0 + bc4;

    for (int kt = 0; kt < K; kt += 8) {
        float4 av = *(const float4*)(Aptr + kt);
        float4 bv = *(const float4*)(Bptr + (size_t)kt * N);
        As[ac4+0][arow] = av.x; As[ac4+1][arow] = av.y;
        As[ac4+2][arow] = av.z; As[ac4+3][arow] = av.w;
        *(float4*)&Bs[brow][bc4] = bv;
        __syncthreads();
        #pragma unroll
        for (int kk = 0; kk < 8; kk++) {
            float4 a0 = *(const float4*)&As[kk][ty*8];
            float4 a1 = *(const float4*)&As[kk][ty*8+4];
            float4 b0 = *(const float4*)&Bs[kk][tx*8];
            float4 b1 = *(const float4*)&Bs[kk][tx*8+4];
            float af[8] = {a0.x,a0.y,a0.z,a0.w,a1.x,a1.y,a1.z,a1.w};
            float bf[8] = {b0.x,b0.y,b0.z,b0.w,b1.x,b1.y,b1.z,b1.w};
            #pragma unroll
            for (int i = 0; i < 8; i++)
                #pragma unroll
                for (int j = 0; j < 8; j++)
                    acc[i][j] = fmaf(af[i], bf[j], acc[i][j]);
        }
        __syncthreads();
    }

    #pragma unroll
    for (int i = 0; i < 8; i++) {
        int m = m0 + ty*8 + i;
        #pragma unroll
        for (int j = 0; j < 8; j++) {
            int n = n0 + tx*8 + j;
            float val = acc[i][j];
            if (EPI == EPI_QKV) {
                int t  = n >> 10;
                int nn = n & 1023;
                int h  = nn >> 6;
                int d  = nn & 63;
                int bb = m >> 11;        // / T
                int tt = m & 2047;       // % T
                size_t o = ((size_t)(bb*HH + h) * TT + tt) * DH + d;
                float* dst = (t == 0) ? oq : (t == 1) ? ok : ov;
                dst[o] = val;
            } else if (EPI == EPI_BIAS_RESID) {
                C[(size_t)m * N + n] = val + bias[n] + resid[(size_t)m * N + n];
            } else { // EPI_BIAS_RELU
                float u = val + bias[n];
                C[(size_t)m * N + n] = u > 0.f ? u : 0.f;
            }
        }
    }
}

// ---------------- Flash attention: 64 queries/block, causal ----------------
// grid (T/64, B*H), 256 threads (16x16), 4x4 microtile. smem stride 68.
__global__ void __launch_bounds__(256) flash_kernel(
    const float* __restrict__ q, const float* __restrict__ k,
    const float* __restrict__ v, float* __restrict__ att)
{
    extern __shared__ float sm[];
    float (*Qs)[68] = (float (*)[68]) sm;                 // [64][68]
    float (*Kt)[68] = (float (*)[68])(sm + 64*68);        // K transposed: Kt[d][s]
    float (*Vs)[68] = (float (*)[68])(sm + 2*64*68);      // Vs[s][c]
    float (*Ps)[68] = (float (*)[68])(sm + 3*64*68);      // Ps[r][s]

    int tid = threadIdx.x;
    int tx = tid & 15, ty = tid >> 4;
    int qt = blockIdx.x;
    int bh = blockIdx.y;
    const float* qp = q + ((size_t)bh * TT + (size_t)qt * 64) * DH;
    const float* kp = k + (size_t)bh * TT * DH;
    const float* vp = v + (size_t)bh * TT * DH;

    // load Q tile (64x64)
    for (int i = tid; i < 1024; i += 256) {
        int r = i >> 4, c4 = (i & 15) * 4;
        *(float4*)&Qs[r][c4] = *(const float4*)(qp + r*64 + c4);
    }

    float O[4][4];
    #pragma unroll
    for (int i = 0; i < 4; i++)
        #pragma unroll
        for (int j = 0; j < 4; j++) O[i][j] = 0.f;
    float mi[4] = {-FLT_MAX, -FLT_MAX, -FLT_MAX, -FLT_MAX};
    float li[4] = {0.f, 0.f, 0.f, 0.f};
    const float scale = 0.03125f;  // E^-0.5 = 1/32 (reference scales by embed dim)

    for (int kt_i = 0; kt_i <= qt; kt_i++) {
        // load K (transposed) and V tiles
        for (int i = tid; i < 1024; i += 256) {
            int r = i >> 4, c4 = (i & 15) * 4;
            float4 kv = *(const float4*)(kp + (size_t)(kt_i*64 + r)*64 + c4);
            Kt[c4+0][r] = kv.x; Kt[c4+1][r] = kv.y;
            Kt[c4+2][r] = kv.z; Kt[c4+3][r] = kv.w;
            *(float4*)&Vs[r][c4] = *(const float4*)(vp + (size_t)(kt_i*64 + r)*64 + c4);
        }
        __syncthreads();

        // S = scale * Q K^T  (4x4 per thread)
        float S[4][4];
        #pragma unroll
        for (int i = 0; i < 4; i++)
            #pragma unroll
            for (int j = 0; j < 4; j++) S[i][j] = 0.f;
        #pragma unroll 8
        for (int d = 0; d < 64; d++) {
            float qf[4];
            #pragma unroll
            for (int i = 0; i < 4; i++) qf[i] = Qs[ty*4+i][d];
            float4 kf = *(const float4*)&Kt[d][tx*4];
            #pragma unroll
            for (int i = 0; i < 4; i++) {
                S[i][0] = fmaf(qf[i], kf.x, S[i][0]);
                S[i][1] = fmaf(qf[i], kf.y, S[i][1]);
                S[i][2] = fmaf(qf[i], kf.z, S[i][2]);
                S[i][3] = fmaf(qf[i], kf.w, S[i][3]);
            }
        }
        bool diag = (kt_i == qt);
        #pragma unroll
        for (int i = 0; i < 4; i++)
            #pragma unroll
            for (int j = 0; j < 4; j++) {
                S[i][j] *= scale;
                if (diag && (tx*4 + j > ty*4 + i)) S[i][j] = -FLT_MAX;
            }

        // online softmax, per-row reduce over the 16 tx lanes
        #pragma unroll
        for (int i = 0; i < 4; i++) {
            float rm = fmaxf(fmaxf(S[i][0], S[i][1]), fmaxf(S[i][2], S[i][3]));
            #pragma unroll
            for (int o = 1; o < 16; o <<= 1)
                rm = fmaxf(rm, __shfl_xor_sync(0xffffffffu, rm, o));
            float mnew = fmaxf(mi[i], rm);
            float alpha = __expf(mi[i] - mnew);
            float rs = 0.f;
            #pragma unroll
            for (int j = 0; j < 4; j++) {
                S[i][j] = __expf(S[i][j] - mnew);
                rs += S[i][j];
            }
            #pragma unroll
            for (int o = 1; o < 16; o <<= 1)
                rs += __shfl_xor_sync(0xffffffffu, rs, o);
            li[i] = li[i] * alpha + rs;
            mi[i] = mnew;
            #pragma unroll
            for (int j = 0; j < 4; j++) O[i][j] *= alpha;
        }

        // stage P
        #pragma unroll
        for (int i = 0; i < 4; i++) {
            float4 pv = make_float4(S[i][0], S[i][1], S[i][2], S[i][3]);
            *(float4*)&Ps[ty*4+i][tx*4] = pv;
        }
        __syncthreads();

        // O += P @ V
        #pragma unroll 8
        for (int s = 0; s < 64; s++) {
            float pf[4];
            #pragma unroll
            for (int i = 0; i < 4; i++) pf[i] = Ps[ty*4+i][s];
            float4 vf = *(const float4*)&Vs[s][tx*4];
            #pragma unroll
            for (int i = 0; i < 4; i++) {
                O[i][0] = fmaf(pf[i], vf.x, O[i][0]);
                O[i][1] = fmaf(pf[i], vf.y, O[i][1]);
                O[i][2] = fmaf(pf[i], vf.z, O[i][2]);
                O[i][3] = fmaf(pf[i], vf.w, O[i][3]);
            }
        }
        __syncthreads();
    }

    // normalize and write att in [B, T, H*64+d] (heads concatenated)
    int b = bh >> 4;
    int h = bh & 15;
    #pragma unroll
    for (int i = 0; i < 4; i++) {
        float inv = 1.0f / li[i];
        int r = qt*64 + ty*4 + i;
        float4 ov = make_float4(O[i][0]*inv, O[i][1]*inv, O[i][2]*inv, O[i][3]*inv);
        *(float4*)(att + ((size_t)(b*TT + r)) * EE + h*64 + tx*4) = ov;
    }
}

// ---------------- launch ----------------------------------------------------
extern "C" void kernel_launch(void* const* d_in, const int* in_sizes, int n_in,
                              void* d_out, int out_size)
{
    const float* x     = (const float*)d_in[0];
    const float* ln1_g = (const float*)d_in[1];
    const float* ln1_b = (const float*)d_in[2];
    const float* Wq    = (const float*)d_in[3];
    const float* Wk    = (const float*)d_in[4];
    const float* Wv    = (const float*)d_in[5];
    const float* Wp    = (const float*)d_in[6];
    const float* bp    = (const float*)d_in[7];
    const float* ln2_g = (const float*)d_in[8];
    const float* ln2_b = (const float*)d_in[9];
    const float* W1    = (const float*)d_in[10];
    const float* b1    = (const float*)d_in[11];
    const float* W2    = (const float*)d_in[12];
    const float* b2    = (const float*)d_in[13];
    float* out = (float*)d_out;

    float *h, *wqkv, *q, *k, *v, *att, *x1, *ffh;
    cudaGetSymbolAddress((void**)&h,    g_h);
    cudaGetSymbolAddress((void**)&wqkv, g_wqkv);
    cudaGetSymbolAddress((void**)&q,    g_q);
    cudaGetSymbolAddress((void**)&k,    g_k);
    cudaGetSymbolAddress((void**)&v,    g_v);
    cudaGetSymbolAddress((void**)&att,  g_att);
    cudaGetSymbolAddress((void**)&x1,   g_x1);
    cudaGetSymbolAddress((void**)&ffh,  g_ffh);

    const int FLASH_SMEM = 4 * 64 * 68 * 4;  // 69632 bytes
    cudaFuncSetAttribute(flash_kernel, cudaFuncAttributeMaxDynamicSharedMemorySize, FLASH_SMEM);

    // 1. LN1
    ln_kernel<<<MROWS, 256>>>(x, ln1_g, ln1_b, h);
    // 2. pack QKV weights
    pack_qkv_kernel<<<(3*1024*1024)/256, 256>>>(Wq, Wk, Wv, wqkv);
    // 3. QKV projection
    sgemm_kernel<EPI_QKV><<<dim3(3072/128, MROWS/128), 256>>>(
        h, wqkv, nullptr, MROWS, 3072, EE, nullptr, nullptr, q, k, v);
    // 4. flash attention
    flash_kernel<<<dim3(TT/64, BB*HH), 256, FLASH_SMEM>>>(q, k, v, att);
    // 5. output projection + residual
    sgemm_kernel<EPI_BIAS_RESID><<<dim3(EE/128, MROWS/128), 256>>>(
        att, Wp, x1, MROWS, EE, EE, bp, x, nullptr, nullptr, nullptr);
    // 6. LN2
    ln_kernel<<<MROWS, 256>>>(x1, ln2_g, ln2_b, h);
    // 7. FFN up + relu
    sgemm_kernel<EPI_BIAS_RELU><<<dim3(4096/128, MROWS/128), 256>>>(
        h, W1, ffh, MROWS, 4096, EE, b1, nullptr, nullptr, nullptr, nullptr);
    // 8. FFN down + residual -> out
    sgemm_kernel<EPI_BIAS_RESID><<<dim3(EE/128, MROWS/128), 256>>>(
        ffh, W2, out, MROWS, EE, 4096, b2, x1, nullptr, nullptr, nullptr);
}

// round 3
// speedup vs baseline: 2.2590x; 2.2590x over previous
#include <cuda_runtime.h>
#include <cuda_bf16.h>
#include <cfloat>
#include <cstdint>
#include <math.h>

#define BB 4
#define TT 2048
#define EE 1024
#define HH 16
#define DH 64
#define MROWS (BB*TT)        // 8192

typedef __nv_bfloat16 bf16;
typedef __nv_bfloat162 bf162;

// ============================ scratch =====================================
__device__ float g_x1  [(size_t)MROWS*EE];
__device__ float g_wqkv[(size_t)EE*3072];
__device__ float g_q   [(size_t)BB*HH*TT*DH];
__device__ float g_k   [(size_t)BB*HH*TT*DH];
__device__ float g_v   [(size_t)BB*HH*TT*DH];
__device__ bf16 g_hh  [(size_t)MROWS*EE];
__device__ bf16 g_hl  [(size_t)MROWS*EE];
__device__ bf16 g_atth[(size_t)MROWS*EE];
__device__ bf16 g_attl[(size_t)MROWS*EE];
__device__ bf16 g_ffhh[(size_t)MROWS*4096];
__device__ bf16 g_ffhl[(size_t)MROWS*4096];
__device__ bf16 g_wqkvTh[(size_t)3072*EE];
__device__ bf16 g_wqkvTl[(size_t)3072*EE];
__device__ bf16 g_WpTh[(size_t)EE*EE];
__device__ bf16 g_WpTl[(size_t)EE*EE];
__device__ bf16 g_W1Th[(size_t)4096*EE];
__device__ bf16 g_W1Tl[(size_t)4096*EE];
__device__ bf16 g_W2Th[(size_t)EE*4096];
__device__ bf16 g_W2Tl[(size_t)EE*4096];

// ============================ helpers =====================================
__device__ __forceinline__ uint32_t smem_to_u32(const void* p) {
    uint32_t a;
    asm("{ .reg .u64 t; cvta.to.shared.u64 t, %1; cvt.u32.u64 %0, t; }"
        : "=r"(a) : "l"(p));
    return a;
}

#define SWZ128(o) ((o) ^ (((o) >> 3) & 0x70))

#define CP16(dst, src) \
    asm volatile("cp.async.cg.shared.global [%0], [%1], 16;" \
        :: "r"(dst), "l"(src) : "memory")
#define CP_COMMIT() asm volatile("cp.async.commit_group;" ::: "memory")
#define CP_WAIT(N)  asm volatile("cp.async.wait_group %0;" :: "n"(N) : "memory")

__device__ __forceinline__ void ldsm_x4(uint32_t addr,
    uint32_t& r0, uint32_t& r1, uint32_t& r2, uint32_t& r3) {
    asm volatile("ldmatrix.sync.aligned.m8n8.x4.shared.b16 {%0,%1,%2,%3}, [%4];"
        : "=r"(r0), "=r"(r1), "=r"(r2), "=r"(r3) : "r"(addr));
}

__device__ __forceinline__ void mma_bf16(float* c, const uint32_t* a, const uint32_t* b) {
    asm volatile(
        "mma.sync.aligned.m16n8k16.row.col.f32.bf16.bf16.f32 "
        "{%0,%1,%2,%3}, {%4,%5,%6,%7}, {%8,%9}, {%0,%1,%2,%3};"
        : "+f"(c[0]), "+f"(c[1]), "+f"(c[2]), "+f"(c[3])
        : "r"(a[0]), "r"(a[1]), "r"(a[2]), "r"(a[3]), "r"(b[0]), "r"(b[1]));
}

__device__ __forceinline__ void split_bf16(float x, bf16& h, bf16& l) {
    h = __float2bfloat16(x);
    l = __float2bfloat16(x - __bfloat162float(h));
}

// ============================ LayerNorm (emits hi/lo bf16) =================
__global__ void __launch_bounds__(256) ln_kernel(
    const float* __restrict__ x, const float* __restrict__ g,
    const float* __restrict__ b, bf16* __restrict__ oh, bf16* __restrict__ ol)
{
    int row = blockIdx.x;
    int tid = threadIdx.x;
    float4 xv = ((const float4*)(x + (size_t)row * EE))[tid];
    float s  = xv.x + xv.y + xv.z + xv.w;
    float s2 = xv.x*xv.x + xv.y*xv.y + xv.z*xv.z + xv.w*xv.w;
    #pragma unroll
    for (int o = 16; o > 0; o >>= 1) {
        s  += __shfl_xor_sync(0xffffffffu, s,  o);
        s2 += __shfl_xor_sync(0xffffffffu, s2, o);
    }
    __shared__ float rs[8], rs2[8];
    int w = tid >> 5;
    if ((tid & 31) == 0) { rs[w] = s; rs2[w] = s2; }
    __syncthreads();
    s = 0.f; s2 = 0.f;
    #pragma unroll
    for (int i = 0; i < 8; i++) { s += rs[i]; s2 += rs2[i]; }
    float mean = s * (1.0f/1024.0f);
    float var  = s2 * (1.0f/1024.0f) - mean*mean;
    float inv  = rsqrtf(var + 1e-5f);
    float4 gv = ((const float4*)g)[tid];
    float4 bv = ((const float4*)b)[tid];
    float o0 = (xv.x - mean)*inv*gv.x + bv.x;
    float o1 = (xv.y - mean)*inv*gv.y + bv.y;
    float o2 = (xv.z - mean)*inv*gv.z + bv.z;
    float o3 = (xv.w - mean)*inv*gv.w + bv.w;
    bf16 h0,l0,h1,l1,h2,l2,h3,l3;
    split_bf16(o0,h0,l0); split_bf16(o1,h1,l1);
    split_bf16(o2,h2,l2); split_bf16(o3,h3,l3);
    size_t base = (size_t)row * EE + tid*4;
    bf162 hp0; hp0.x=h0; hp0.y=h1;  bf162 hp1; hp1.x=h2; hp1.y=h3;
    bf162 lp0; lp0.x=l0; lp0.y=l1;  bf162 lp1; lp1.x=l2; lp1.y=l3;
    *(bf162*)(oh+base) = hp0; *(bf162*)(oh+base+2) = hp1;
    *(bf162*)(ol+base) = lp0; *(bf162*)(ol+base+2) = lp1;
}

// ============== pack Wq/Wk/Wv -> fp32 [E rows, 3072 cols] ==================
__global__ void pack_qkv_kernel(const float* __restrict__ Wq,
                                const float* __restrict__ Wk,
                                const float* __restrict__ Wv,
                                float* __restrict__ Wpk)
{
    int i = blockIdx.x * 256 + threadIdx.x;
    int e  = i / 3072;
    int n  = i % 3072;
    int t  = n >> 10;
    int nn = n & 1023;
    int h  = nn >> 6;
    int d  = nn & 63;
    const float* W = (t == 0) ? Wq : (t == 1) ? Wk : Wv;
    Wpk[i] = W[(size_t)h * EE * DH + (size_t)e * DH + d];
}

// ======== transpose + hi/lo split: src fp32 [K,N] -> dst bf16 [N,K] ========
__global__ void __launch_bounds__(256) convt_kernel(
    const float* __restrict__ src, bf16* __restrict__ dh, bf16* __restrict__ dl,
    int K, int N)
{
    __shared__ float t[32][33];
    int x = threadIdx.x & 31, y = threadIdx.x >> 5;
    int n0 = blockIdx.x * 32, k0 = blockIdx.y * 32;
    #pragma unroll
    for (int i = 0; i < 32; i += 8)
        t[y+i][x] = src[(size_t)(k0 + y + i) * N + n0 + x];
    __syncthreads();
    #pragma unroll
    for (int i = 0; i < 32; i += 8) {
        float vv = t[x][y+i];
        bf16 hb, lb; split_bf16(vv, hb, lb);
        size_t o = (size_t)(n0 + y + i) * K + k0 + x;
        dh[o] = hb; dl[o] = lb;
    }
}

// ============ HMMA GEMM: C[M,N] = A[M,K] * Bt[N,K]^T (hi/lo bf16) ==========
enum { EPI_QKV = 0, EPI_BIAS_RESID = 1, EPI_RELU_SPLIT = 2 };

#define KCHUNK 64
#define TILE_BYTES 16384                 // 128 rows x 64 bf16
#define STAGE_BYTES (4*TILE_BYTES)       // Ah Al Bh Bl
#define SMEM_GEMM (2*STAGE_BYTES + 1024) // 132096

template<int EPI>
__global__ void __launch_bounds__(256, 1) gemm_tc(
    const bf16* __restrict__ Ah, const bf16* __restrict__ Al,
    const bf16* __restrict__ Bh, const bf16* __restrict__ Bl,
    int K, int N,
    const float* __restrict__ bias, const float* __restrict__ resid,
    float* __restrict__ Cf, bf16* __restrict__ Oh, bf16* __restrict__ Ol,
    float* __restrict__ oq, float* __restrict__ okk, float* __restrict__ ovv)
{
    extern __shared__ char smraw[];
    uint32_t raw = smem_to_u32(smraw);
    uint32_t sbase = (raw + 1023u) & ~1023u;

    int tid  = threadIdx.x;
    int wid  = tid >> 5, lane = tid & 31;
    int m0 = blockIdx.y * 128;
    int n0 = blockIdx.x * 128;
    int mw = (wid & 1) * 64;       // warp row offset
    int nw = (wid >> 1) * 32;      // warp col offset

    const bf16* gptr[4];
    gptr[0] = Ah + (size_t)m0 * K;
    gptr[1] = Al + (size_t)m0 * K;
    gptr[2] = Bh + (size_t)n0 * K;
    gptr[3] = Bl + (size_t)n0 * K;

    const int nk = K / KCHUNK;

    auto prefetch = [&](int c) {
        uint32_t st = sbase + (uint32_t)(c & 1) * STAGE_BYTES;
        int kc = c * KCHUNK;
        #pragma unroll
        for (int t = 0; t < 4; t++) {
            #pragma unroll
            for (int it = 0; it < 4; it++) {
                int u = tid + it * 256;           // 1024 16B-units per tile
                int r = u >> 3, cc = u & 7;
                uint32_t so = st + (uint32_t)t * TILE_BYTES
                            + SWZ128((uint32_t)(r * 128 + cc * 16));
                CP16(so, gptr[t] + (size_t)r * K + kc + cc * 8);
            }
        }
    };

    float acc[4][4][4];
    #pragma unroll
    for (int mt = 0; mt < 4; mt++)
        #pragma unroll
        for (int nt = 0; nt < 4; nt++)
            #pragma unroll
            for (int q = 0; q < 4; q++) acc[mt][nt][q] = 0.f;

    prefetch(0);
    CP_COMMIT();

    int g  = lane >> 3;   // ldmatrix lane group
    int lr = lane & 7;

    for (int c = 0; c < nk; c++) {
        if (c + 1 < nk) {
            prefetch(c + 1);
            CP_COMMIT();
            CP_WAIT(1);
        } else {
            CP_WAIT(0);
        }
        __syncthreads();

        uint32_t st = sbase + (uint32_t)(c & 1) * STAGE_BYTES;
        uint32_t aH = st, aL = st + TILE_BYTES;
        uint32_t bH = st + 2*TILE_BYTES, bL = st + 3*TILE_BYTES;

        #pragma unroll
        for (int ks = 0; ks < 4; ks++) {
            uint32_t ah[4][4], al[4][4], bh[4][2], bl[4][2];
            #pragma unroll
            for (int mt = 0; mt < 4; mt++) {
                uint32_t off = SWZ128((uint32_t)(
                    (mw + mt*16 + (g & 1)*8 + lr) * 128 + ks*32 + (g >> 1)*16));
                ldsm_x4(aH + off, ah[mt][0], ah[mt][1], ah[mt][2], ah[mt][3]);
                ldsm_x4(aL + off, al[mt][0], al[mt][1], al[mt][2], al[mt][3]);
            }
            #pragma unroll
            for (int p = 0; p < 2; p++) {
                uint32_t off = SWZ128((uint32_t)(
                    (nw + p*16 + (g >> 1)*8 + lr) * 128 + ks*32 + (g & 1)*16));
                uint32_t r0, r1, r2, r3;
                ldsm_x4(bH + off, r0, r1, r2, r3);
                bh[p*2][0] = r0; bh[p*2][1] = r1;
                bh[p*2+1][0] = r2; bh[p*2+1][1] = r3;
                ldsm_x4(bL + off, r0, r1, r2, r3);
                bl[p*2][0] = r0; bl[p*2][1] = r1;
                bl[p*2+1][0] = r2; bl[p*2+1][1] = r3;
            }
            #pragma unroll
            for (int mt = 0; mt < 4; mt++)
                #pragma unroll
                for (int nt = 0; nt < 4; nt++) {
                    mma_bf16(acc[mt][nt], ah[mt], bh[nt]);
                    mma_bf16(acc[mt][nt], ah[mt], bl[nt]);
                    mma_bf16(acc[mt][nt], al[mt], bh[nt]);
                }
        }
        __syncthreads();
    }

    // ------------------------------ epilogue -------------------------------
    int qr = lane >> 2;        // 0..7
    int qc = (lane & 3) * 2;   // 0,2,4,6
    #pragma unroll
    for (int mt = 0; mt < 4; mt++) {
        #pragma unroll
        for (int nt = 0; nt < 4; nt++) {
            int col = n0 + nw + nt*8 + qc;
            #pragma unroll
            for (int half = 0; half < 2; half++) {
                int m = m0 + mw + mt*16 + qr + half*8;
                float v0 = acc[mt][nt][half*2 + 0];
                float v1 = acc[mt][nt][half*2 + 1];
                if (EPI == EPI_QKV) {
                    int bb = m >> 11, tt = m & 2047;
                    int t = col >> 10, nn = col & 1023, h = nn >> 6, d0 = nn & 63;
                    float* dst = (t == 0 ? oq : t == 1 ? okk : ovv)
                               + (((size_t)(bb*HH + h)) * TT + tt) * DH + d0;
                    dst[0] = v0; dst[1] = v1;
                } else if (EPI == EPI_BIAS_RESID) {
                    size_t o = (size_t)m * N + col;
                    float2 r2 = *(const float2*)(resid + o);
                    float2 w2;
                    w2.x = v0 + bias[col]     + r2.x;
                    w2.y = v1 + bias[col + 1] + r2.y;
                    *(float2*)(Cf + o) = w2;
                } else { // EPI_RELU_SPLIT
                    size_t o = (size_t)m * N + col;
                    float u0 = fmaxf(v0 + bias[col],     0.f);
                    float u1 = fmaxf(v1 + bias[col + 1], 0.f);
                    bf16 h0, l0, h1, l1;
                    split_bf16(u0, h0, l0); split_bf16(u1, h1, l1);
                    bf162 hp; hp.x = h0; hp.y = h1;
                    bf162 lp; lp.x = l0; lp.y = l1;
                    *(bf162*)(Oh + o) = hp;
                    *(bf162*)(Ol + o) = lp;
                }
            }
        }
    }
}

// ================= flash attention (fp32 SIMT, emits hi/lo) ================
__global__ void __launch_bounds__(256) flash_kernel(
    const float* __restrict__ q, const float* __restrict__ k,
    const float* __restrict__ v, bf16* __restrict__ atth, bf16* __restrict__ attl)
{
    extern __shared__ float sm[];
    float (*Qs)[68] = (float (*)[68]) sm;
    float (*Kt)[68] = (float (*)[68])(sm + 64*68);
    float (*Vs)[68] = (float (*)[68])(sm + 2*64*68);
    float (*Ps)[68] = (float (*)[68])(sm + 3*64*68);

    int tid = threadIdx.x;
    int tx = tid & 15, ty = tid >> 4;
    int qt = blockIdx.x;
    int bh = blockIdx.y;
    const float* qp = q + ((size_t)bh * TT + (size_t)qt * 64) * DH;
    const float* kp = k + (size_t)bh * TT * DH;
    const float* vp = v + (size_t)bh * TT * DH;

    for (int i = tid; i < 1024; i += 256) {
        int r = i >> 4, c4 = (i & 15) * 4;
        *(float4*)&Qs[r][c4] = *(const float4*)(qp + r*64 + c4);
    }

    float O[4][4];
    #pragma unroll
    for (int i = 0; i < 4; i++)
        #pragma unroll
        for (int j = 0; j < 4; j++) O[i][j] = 0.f;
    float mi[4] = {-FLT_MAX, -FLT_MAX, -FLT_MAX, -FLT_MAX};
    float li[4] = {0.f, 0.f, 0.f, 0.f};
    const float scale = 0.03125f;

    for (int kt_i = 0; kt_i <= qt; kt_i++) {
        for (int i = tid; i < 1024; i += 256) {
            int r = i >> 4, c4 = (i & 15) * 4;
            float4 kv = *(const float4*)(kp + (size_t)(kt_i*64 + r)*64 + c4);
            Kt[c4+0][r] = kv.x; Kt[c4+1][r] = kv.y;
            Kt[c4+2][r] = kv.z; Kt[c4+3][r] = kv.w;
            *(float4*)&Vs[r][c4] = *(const float4*)(vp + (size_t)(kt_i*64 + r)*64 + c4);
        }
        __syncthreads();

        float S[4][4];
        #pragma unroll
        for (int i = 0; i < 4; i++)
            #pragma unroll
            for (int j = 0; j < 4; j++) S[i][j] = 0.f;
        #pragma unroll 8
        for (int d = 0; d < 64; d++) {
            float qf[4];
            #pragma unroll
            for (int i = 0; i < 4; i++) qf[i] = Qs[ty*4+i][d];
            float4 kf = *(const float4*)&Kt[d][tx*4];
            #pragma unroll
            for (int i = 0; i < 4; i++) {
                S[i][0] = fmaf(qf[i], kf.x, S[i][0]);
                S[i][1] = fmaf(qf[i], kf.y, S[i][1]);
                S[i][2] = fmaf(qf[i], kf.z, S[i][2]);
                S[i][3] = fmaf(qf[i], kf.w, S[i][3]);
            }
        }
        bool diag = (kt_i == qt);
        #pragma unroll
        for (int i = 0; i < 4; i++)
            #pragma unroll
            for (int j = 0; j < 4; j++) {
                S[i][j] *= scale;
                if (diag && (tx*4 + j > ty*4 + i)) S[i][j] = -FLT_MAX;
            }

        #pragma unroll
        for (int i = 0; i < 4; i++) {
            float rm = fmaxf(fmaxf(S[i][0], S[i][1]), fmaxf(S[i][2], S[i][3]));
            #pragma unroll
            for (int o = 1; o < 16; o <<= 1)
                rm = fmaxf(rm, __shfl_xor_sync(0xffffffffu, rm, o));
            float mnew = fmaxf(mi[i], rm);
            float alpha = __expf(mi[i] - mnew);
            float rs = 0.f;
            #pragma unroll
            for (int j = 0; j < 4; j++) {
                S[i][j] = __expf(S[i][j] - mnew);
                rs += S[i][j];
            }
            #pragma unroll
            for (int o = 1; o < 16; o <<= 1)
                rs += __shfl_xor_sync(0xffffffffu, rs, o);
            li[i] = li[i] * alpha + rs;
            mi[i] = mnew;
            #pragma unroll
            for (int j = 0; j < 4; j++) O[i][j] *= alpha;
        }

        #pragma unroll
        for (int i = 0; i < 4; i++)
            *(float4*)&Ps[ty*4+i][tx*4] = make_float4(S[i][0], S[i][1], S[i][2], S[i][3]);
        __syncthreads();

        #pragma unroll 8
        for (int s = 0; s < 64; s++) {
            float pf[4];
            #pragma unroll
            for (int i = 0; i < 4; i++) pf[i] = Ps[ty*4+i][s];
            float4 vf = *(const float4*)&Vs[s][tx*4];
            #pragma unroll
            for (int i = 0; i < 4; i++) {
                O[i][0] = fmaf(pf[i], vf.x, O[i][0]);
                O[i][1] = fmaf(pf[i], vf.y, O[i][1]);
                O[i][2] = fmaf(pf[i], vf.z, O[i][2]);
                O[i][3] = fmaf(pf[i], vf.w, O[i][3]);
            }
        }
        __syncthreads();
    }

    int b = bh >> 4;
    int h = bh & 15;
    #pragma unroll
    for (int i = 0; i < 4; i++) {
        float inv = 1.0f / li[i];
        int r = qt*64 + ty*4 + i;
        float o0 = O[i][0]*inv, o1 = O[i][1]*inv, o2 = O[i][2]*inv, o3 = O[i][3]*inv;
        bf16 h0,l0,h1,l1,h2,l2,h3,l3;
        split_bf16(o0,h0,l0); split_bf16(o1,h1,l1);
        split_bf16(o2,h2,l2); split_bf16(o3,h3,l3);
        size_t base = ((size_t)(b*TT + r)) * EE + h*64 + tx*4;
        bf162 hp0; hp0.x=h0; hp0.y=h1;  bf162 hp1; hp1.x=h2; hp1.y=h3;
        bf162 lp0; lp0.x=l0; lp0.y=l1;  bf162 lp1; lp1.x=l2; lp1.y=l3;
        *(bf162*)(atth+base) = hp0; *(bf162*)(atth+base+2) = hp1;
        *(bf162*)(attl+base) = lp0; *(bf162*)(attl+base+2) = lp1;
    }
}

// ============================== launch =====================================
extern "C" void kernel_launch(void* const* d_in, const int* in_sizes, int n_in,
                              void* d_out, int out_size)
{
    const float* x     = (const float*)d_in[0];
    const float* ln1_g = (const float*)d_in[1];
    const float* ln1_b = (const float*)d_in[2];
    const float* Wq    = (const float*)d_in[3];
    const float* Wk    = (const float*)d_in[4];
    const float* Wv    = (const float*)d_in[5];
    const float* Wp    = (const float*)d_in[6];
    const float* bp    = (const float*)d_in[7];
    const float* ln2_g = (const float*)d_in[8];
    const float* ln2_b = (const float*)d_in[9];
    const float* W1    = (const float*)d_in[10];
    const float* b1    = (const float*)d_in[11];
    const float* W2    = (const float*)d_in[12];
    const float* b2    = (const float*)d_in[13];
    float* out = (float*)d_out;

    float *x1, *wqkv, *q, *k, *v;
    bf16 *hh, *hl, *atth, *attl, *ffhh, *ffhl;
    bf16 *wqTh, *wqTl, *WpTh, *WpTl, *W1Th, *W1Tl, *W2Th, *W2Tl;
    cudaGetSymbolAddress((void**)&x1,   g_x1);
    cudaGetSymbolAddress((void**)&wqkv, g_wqkv);
    cudaGetSymbolAddress((void**)&q,    g_q);
    cudaGetSymbolAddress((void**)&k,    g_k);
    cudaGetSymbolAddress((void**)&v,    g_v);
    cudaGetSymbolAddress((void**)&hh,   g_hh);
    cudaGetSymbolAddress((void**)&hl,   g_hl);
    cudaGetSymbolAddress((void**)&atth, g_atth);
    cudaGetSymbolAddress((void**)&attl, g_attl);
    cudaGetSymbolAddress((void**)&ffhh, g_ffhh);
    cudaGetSymbolAddress((void**)&ffhl, g_ffhl);
    cudaGetSymbolAddress((void**)&wqTh, g_wqkvTh);
    cudaGetSymbolAddress((void**)&wqTl, g_wqkvTl);
    cudaGetSymbolAddress((void**)&WpTh, g_WpTh);
    cudaGetSymbolAddress((void**)&WpTl, g_WpTl);
    cudaGetSymbolAddress((void**)&W1Th, g_W1Th);
    cudaGetSymbolAddress((void**)&W1Tl, g_W1Tl);
    cudaGetSymbolAddress((void**)&W2Th, g_W2Th);
    cudaGetSymbolAddress((void**)&W2Tl, g_W2Tl);

    const int FLASH_SMEM = 4 * 64 * 68 * 4;
    cudaFuncSetAttribute(flash_kernel, cudaFuncAttributeMaxDynamicSharedMemorySize, FLASH_SMEM);
    cudaFuncSetAttribute(gemm_tc<EPI_QKV>,        cudaFuncAttributeMaxDynamicSharedMemorySize, SMEM_GEMM);
    cudaFuncSetAttribute(gemm_tc<EPI_BIAS_RESID>, cudaFuncAttributeMaxDynamicSharedMemorySize, SMEM_GEMM);
    cudaFuncSetAttribute(gemm_tc<EPI_RELU_SPLIT>, cudaFuncAttributeMaxDynamicSharedMemorySize, SMEM_GEMM);

    // weight prep
    pack_qkv_kernel<<<(3*1024*1024)/256, 256>>>(Wq, Wk, Wv, wqkv);
    convt_kernel<<<dim3(3072/32, 1024/32), 256>>>(wqkv, wqTh, wqTl, 1024, 3072);
    convt_kernel<<<dim3(1024/32, 1024/32), 256>>>(Wp, WpTh, WpTl, 1024, 1024);
    convt_kernel<<<dim3(4096/32, 1024/32), 256>>>(W1, W1Th, W1Tl, 1024, 4096);
    convt_kernel<<<dim3(1024/32, 4096/32), 256>>>(W2, W2Th, W2Tl, 4096, 1024);

    // 1. LN1 -> hi/lo
    ln_kernel<<<MROWS, 256>>>(x, ln1_g, ln1_b, hh, hl);
    // 2. QKV projection (HMMA) -> q,k,v fp32
    gemm_tc<EPI_QKV><<<dim3(3072/128, MROWS/128), 256, SMEM_GEMM>>>(
        hh, hl, wqTh, wqTl, 1024, 3072, nullptr, nullptr,
        nullptr, nullptr, nullptr, q, k, v);
    // 3. flash attention -> att hi/lo
    flash_kernel<<<dim3(TT/64, BB*HH), 256, FLASH_SMEM>>>(q, k, v, atth, attl);
    // 4. out-proj + bias + residual -> x1
    gemm_tc<EPI_BIAS_RESID><<<dim3(1024/128, MROWS/128), 256, SMEM_GEMM>>>(
        atth, attl, WpTh, WpTl, 1024, 1024, bp, x,
        x1, nullptr, nullptr, nullptr, nullptr, nullptr);
    // 5. LN2 -> hi/lo
    ln_kernel<<<MROWS, 256>>>(x1, ln2_g, ln2_b, hh, hl);
    // 6. FFN up + relu -> ffh hi/lo
    gemm_tc<EPI_RELU_SPLIT><<<dim3(4096/128, MROWS/128), 256, SMEM_GEMM>>>(
        hh, hl, W1Th, W1Tl, 1024, 4096, b1, nullptr,
        nullptr, ffhh, ffhl, nullptr, nullptr, nullptr);
    // 7. FFN down + bias + residual -> out
    gemm_tc<EPI_BIAS_RESID><<<dim3(1024/128, MROWS/128), 256, SMEM_GEMM>>>(
        ffhh, ffhl, W2Th, W2Tl, 4096, 1024, b2, x1,
        out, nullptr, nullptr, nullptr, nullptr, nullptr);
}

// round 4
// speedup vs baseline: 3.1954x; 1.4145x over previous
#include <cuda_runtime.h>
#include <cuda_bf16.h>
#include <cfloat>
#include <cstdint>
#include <math.h>

#define BB 4
#define TT 2048
#define EE 1024
#define HH 16
#define DH 64
#define MROWS (BB*TT)        // 8192

typedef __nv_bfloat16 bf16;
typedef __nv_bfloat162 bf162;

// ============================ scratch =====================================
__device__ float g_x1  [(size_t)MROWS*EE];
__device__ float g_wqkv[(size_t)EE*3072];
__device__ float g_v   [(size_t)BB*HH*TT*DH];
__device__ bf16 g_qh  [(size_t)BB*HH*TT*DH];
__device__ bf16 g_ql  [(size_t)BB*HH*TT*DH];
__device__ bf16 g_kh  [(size_t)BB*HH*TT*DH];
__device__ bf16 g_kl  [(size_t)BB*HH*TT*DH];
__device__ bf16 g_vth [(size_t)BB*HH*DH*TT];
__device__ bf16 g_vtl [(size_t)BB*HH*DH*TT];
__device__ bf16 g_hh  [(size_t)MROWS*EE];
__device__ bf16 g_hl  [(size_t)MROWS*EE];
__device__ bf16 g_atth[(size_t)MROWS*EE];
__device__ bf16 g_attl[(size_t)MROWS*EE];
__device__ bf16 g_ffhh[(size_t)MROWS*4096];
__device__ bf16 g_ffhl[(size_t)MROWS*4096];
__device__ bf16 g_wqkvTh[(size_t)3072*EE];
__device__ bf16 g_wqkvTl[(size_t)3072*EE];
__device__ bf16 g_WpTh[(size_t)EE*EE];
__device__ bf16 g_WpTl[(size_t)EE*EE];
__device__ bf16 g_W1Th[(size_t)4096*EE];
__device__ bf16 g_W1Tl[(size_t)4096*EE];
__device__ bf16 g_W2Th[(size_t)EE*4096];
__device__ bf16 g_W2Tl[(size_t)EE*4096];

// ============================ helpers =====================================
__device__ __forceinline__ uint32_t smem_to_u32(const void* p) {
    uint32_t a;
    asm("{ .reg .u64 t; cvta.to.shared.u64 t, %1; cvt.u32.u64 %0, t; }"
        : "=r"(a) : "l"(p));
    return a;
}

#define SWZ128(o) ((o) ^ (((o) >> 3) & 0x70))

#define CP16(dst, src) \
    asm volatile("cp.async.cg.shared.global [%0], [%1], 16;" \
        :: "r"(dst), "l"(src) : "memory")
#define CP_COMMIT() asm volatile("cp.async.commit_group;" ::: "memory")
#define CP_WAIT(N)  asm volatile("cp.async.wait_group %0;" :: "n"(N) : "memory")

__device__ __forceinline__ void ldsm_x4(uint32_t addr,
    uint32_t& r0, uint32_t& r1, uint32_t& r2, uint32_t& r3) {
    asm volatile("ldmatrix.sync.aligned.m8n8.x4.shared.b16 {%0,%1,%2,%3}, [%4];"
        : "=r"(r0), "=r"(r1), "=r"(r2), "=r"(r3) : "r"(addr));
}

__device__ __forceinline__ void mma_bf16(float* c, const uint32_t* a, const uint32_t* b) {
    asm volatile(
        "mma.sync.aligned.m16n8k16.row.col.f32.bf16.bf16.f32 "
        "{%0,%1,%2,%3}, {%4,%5,%6,%7}, {%8,%9}, {%0,%1,%2,%3};"
        : "+f"(c[0]), "+f"(c[1]), "+f"(c[2]), "+f"(c[3])
        : "r"(a[0]), "r"(a[1]), "r"(a[2]), "r"(a[3]), "r"(b[0]), "r"(b[1]));
}

__device__ __forceinline__ void split_bf16(float x, bf16& h, bf16& l) {
    h = __float2bfloat16(x);
    l = __float2bfloat16(x - __bfloat162float(h));
}
__device__ __forceinline__ uint32_t pack_bf16x2(bf16 a, bf16 b) {
    uint16_t ra = *reinterpret_cast<uint16_t*>(&a);
    uint16_t rb = *reinterpret_cast<uint16_t*>(&b);
    return (uint32_t)ra | ((uint32_t)rb << 16);
}
__device__ __forceinline__ void split_pack2(float x, float y,
                                            uint32_t& h, uint32_t& l) {
    bf16 xh, xl, yh, yl;
    split_bf16(x, xh, xl); split_bf16(y, yh, yl);
    h = pack_bf16x2(xh, yh);
    l = pack_bf16x2(xl, yl);
}

// ============================ LayerNorm (emits hi/lo bf16) =================
__global__ void __launch_bounds__(256) ln_kernel(
    const float* __restrict__ x, const float* __restrict__ g,
    const float* __restrict__ b, bf16* __restrict__ oh, bf16* __restrict__ ol)
{
    int row = blockIdx.x;
    int tid = threadIdx.x;
    float4 xv = ((const float4*)(x + (size_t)row * EE))[tid];
    float s  = xv.x + xv.y + xv.z + xv.w;
    float s2 = xv.x*xv.x + xv.y*xv.y + xv.z*xv.z + xv.w*xv.w;
    #pragma unroll
    for (int o = 16; o > 0; o >>= 1) {
        s  += __shfl_xor_sync(0xffffffffu, s,  o);
        s2 += __shfl_xor_sync(0xffffffffu, s2, o);
    }
    __shared__ float rs[8], rs2[8];
    int w = tid >> 5;
    if ((tid & 31) == 0) { rs[w] = s; rs2[w] = s2; }
    __syncthreads();
    s = 0.f; s2 = 0.f;
    #pragma unroll
    for (int i = 0; i < 8; i++) { s += rs[i]; s2 += rs2[i]; }
    float mean = s * (1.0f/1024.0f);
    float var  = s2 * (1.0f/1024.0f) - mean*mean;
    float inv  = rsqrtf(var + 1e-5f);
    float4 gv = ((const float4*)g)[tid];
    float4 bv = ((const float4*)b)[tid];
    float o0 = (xv.x - mean)*inv*gv.x + bv.x;
    float o1 = (xv.y - mean)*inv*gv.y + bv.y;
    float o2 = (xv.z - mean)*inv*gv.z + bv.z;
    float o3 = (xv.w - mean)*inv*gv.w + bv.w;
    bf16 h0,l0,h1,l1,h2,l2,h3,l3;
    split_bf16(o0,h0,l0); split_bf16(o1,h1,l1);
    split_bf16(o2,h2,l2); split_bf16(o3,h3,l3);
    size_t base = (size_t)row * EE + tid*4;
    bf162 hp0; hp0.x=h0; hp0.y=h1;  bf162 hp1; hp1.x=h2; hp1.y=h3;
    bf162 lp0; lp0.x=l0; lp0.y=l1;  bf162 lp1; lp1.x=l2; lp1.y=l3;
    *(bf162*)(oh+base) = hp0; *(bf162*)(oh+base+2) = hp1;
    *(bf162*)(ol+base) = lp0; *(bf162*)(ol+base+2) = lp1;
}

// ============== pack Wq/Wk/Wv -> fp32 [E rows, 3072 cols] ==================
__global__ void pack_qkv_kernel(const float* __restrict__ Wq,
                                const float* __restrict__ Wk,
                                const float* __restrict__ Wv,
                                float* __restrict__ Wpk)
{
    int i = blockIdx.x * 256 + threadIdx.x;
    int e  = i / 3072;
    int n  = i % 3072;
    int t  = n >> 10;
    int nn = n & 1023;
    int h  = nn >> 6;
    int d  = nn & 63;
    const float* W = (t == 0) ? Wq : (t == 1) ? Wk : Wv;
    Wpk[i] = W[(size_t)h * EE * DH + (size_t)e * DH + d];
}

// ======== transpose + hi/lo split: src fp32 [K,N] -> dst bf16 [N,K] ========
__global__ void __launch_bounds__(256) convt_kernel(
    const float* __restrict__ src, bf16* __restrict__ dh, bf16* __restrict__ dl,
    int K, int N)
{
    __shared__ float t[32][33];
    int x = threadIdx.x & 31, y = threadIdx.x >> 5;
    int n0 = blockIdx.x * 32, k0 = blockIdx.y * 32;
    #pragma unroll
    for (int i = 0; i < 32; i += 8)
        t[y+i][x] = src[(size_t)(k0 + y + i) * N + n0 + x];
    __syncthreads();
    #pragma unroll
    for (int i = 0; i < 32; i += 8) {
        float vv = t[x][y+i];
        bf16 hb, lb; split_bf16(vv, hb, lb);
        size_t o = (size_t)(n0 + y + i) * K + k0 + x;
        dh[o] = hb; dl[o] = lb;
    }
}

// ===== V transpose: v fp32 [BH, T, DH] -> vth/vtl bf16 [BH, DH, T] =========
__global__ void __launch_bounds__(256) vt_kernel(
    const float* __restrict__ v, bf16* __restrict__ vth, bf16* __restrict__ vtl)
{
    __shared__ float t[32][33];
    int x = threadIdx.x & 31, y = threadIdx.x >> 5;
    int bh = blockIdx.z;
    int t0 = blockIdx.x * 32, d0 = blockIdx.y * 32;
    const float* src = v + (size_t)bh * TT * DH;
    #pragma unroll
    for (int i = 0; i < 32; i += 8)
        t[y+i][x] = src[(size_t)(t0 + y + i) * DH + d0 + x];
    __syncthreads();
    #pragma unroll
    for (int i = 0; i < 32; i += 8) {
        float vv = t[x][y+i];   // = v[t0+x][d0+y+i]
        bf16 hb, lb; split_bf16(vv, hb, lb);
        size_t o = ((size_t)bh * DH + d0 + y + i) * TT + t0 + x;
        vth[o] = hb; vtl[o] = lb;
    }
}

// ============ HMMA GEMM: C[M,N] = A[M,K] * Bt[N,K]^T (hi/lo bf16) ==========
enum { EPI_QKV = 0, EPI_BIAS_RESID = 1, EPI_RELU_SPLIT = 2 };

#define KCHUNK 64
#define TILE_BYTES 16384                 // 128 rows x 64 bf16
#define STAGE_BYTES (4*TILE_BYTES)       // Ah Al Bh Bl
#define SMEM_GEMM (2*STAGE_BYTES + 1024) // 132096

template<int EPI>
__global__ void __launch_bounds__(256, 1) gemm_tc(
    const bf16* __restrict__ Ah, const bf16* __restrict__ Al,
    const bf16* __restrict__ Bh, const bf16* __restrict__ Bl,
    int K, int N,
    const float* __restrict__ bias, const float* __restrict__ resid,
    float* __restrict__ Cf, bf16* __restrict__ Oh, bf16* __restrict__ Ol,
    bf16* __restrict__ oqh, bf16* __restrict__ oql,
    bf16* __restrict__ okh, bf16* __restrict__ okl,
    float* __restrict__ ovv)
{
    extern __shared__ char smraw[];
    uint32_t raw = smem_to_u32(smraw);
    uint32_t sbase = (raw + 1023u) & ~1023u;

    int tid  = threadIdx.x;
    int wid  = tid >> 5, lane = tid & 31;
    int m0 = blockIdx.y * 128;
    int n0 = blockIdx.x * 128;
    int mw = (wid & 1) * 64;       // warp row offset
    int nw = (wid >> 1) * 32;      // warp col offset

    const bf16* gptr[4];
    gptr[0] = Ah + (size_t)m0 * K;
    gptr[1] = Al + (size_t)m0 * K;
    gptr[2] = Bh + (size_t)n0 * K;
    gptr[3] = Bl + (size_t)n0 * K;

    const int nk = K / KCHUNK;

    auto prefetch = [&](int c) {
        uint32_t st = sbase + (uint32_t)(c & 1) * STAGE_BYTES;
        int kc = c * KCHUNK;
        #pragma unroll
        for (int t = 0; t < 4; t++) {
            #pragma unroll
            for (int it = 0; it < 4; it++) {
                int u = tid + it * 256;           // 1024 16B-units per tile
                int r = u >> 3, cc = u & 7;
                uint32_t so = st + (uint32_t)t * TILE_BYTES
                            + SWZ128((uint32_t)(r * 128 + cc * 16));
                CP16(so, gptr[t] + (size_t)r * K + kc + cc * 8);
            }
        }
    };

    float acc[4][4][4];
    #pragma unroll
    for (int mt = 0; mt < 4; mt++)
        #pragma unroll
        for (int nt = 0; nt < 4; nt++)
            #pragma unroll
            for (int q = 0; q < 4; q++) acc[mt][nt][q] = 0.f;

    prefetch(0);
    CP_COMMIT();

    int g  = lane >> 3;   // ldmatrix lane group
    int lr = lane & 7;

    for (int c = 0; c < nk; c++) {
        if (c + 1 < nk) {
            prefetch(c + 1);
            CP_COMMIT();
            CP_WAIT(1);
        } else {
            CP_WAIT(0);
        }
        __syncthreads();

        uint32_t st = sbase + (uint32_t)(c & 1) * STAGE_BYTES;
        uint32_t aH = st, aL = st + TILE_BYTES;
        uint32_t bH = st + 2*TILE_BYTES, bL = st + 3*TILE_BYTES;

        #pragma unroll
        for (int ks = 0; ks < 4; ks++) {
            uint32_t ah[4][4], al[4][4], bh[4][2], bl[4][2];
            #pragma unroll
            for (int mt = 0; mt < 4; mt++) {
                uint32_t off = SWZ128((uint32_t)(
                    (mw + mt*16 + (g & 1)*8 + lr) * 128 + ks*32 + (g >> 1)*16));
                ldsm_x4(aH + off, ah[mt][0], ah[mt][1], ah[mt][2], ah[mt][3]);
                ldsm_x4(aL + off, al[mt][0], al[mt][1], al[mt][2], al[mt][3]);
            }
            #pragma unroll
            for (int p = 0; p < 2; p++) {
                uint32_t off = SWZ128((uint32_t)(
                    (nw + p*16 + (g >> 1)*8 + lr) * 128 + ks*32 + (g & 1)*16));
                uint32_t r0, r1, r2, r3;
                ldsm_x4(bH + off, r0, r1, r2, r3);
                bh[p*2][0] = r0; bh[p*2][1] = r1;
                bh[p*2+1][0] = r2; bh[p*2+1][1] = r3;
                ldsm_x4(bL + off, r0, r1, r2, r3);
                bl[p*2][0] = r0; bl[p*2][1] = r1;
                bl[p*2+1][0] = r2; bl[p*2+1][1] = r3;
            }
            #pragma unroll
            for (int mt = 0; mt < 4; mt++)
                #pragma unroll
                for (int nt = 0; nt < 4; nt++) {
                    mma_bf16(acc[mt][nt], ah[mt], bh[nt]);
                    mma_bf16(acc[mt][nt], ah[mt], bl[nt]);
                    mma_bf16(acc[mt][nt], al[mt], bh[nt]);
                }
        }
        __syncthreads();
    }

    // ------------------------------ epilogue -------------------------------
    int qr = lane >> 2;        // 0..7
    int qc = (lane & 3) * 2;   // 0,2,4,6
    #pragma unroll
    for (int mt = 0; mt < 4; mt++) {
        #pragma unroll
        for (int nt = 0; nt < 4; nt++) {
            int col = n0 + nw + nt*8 + qc;
            #pragma unroll
            for (int half = 0; half < 2; half++) {
                int m = m0 + mw + mt*16 + qr + half*8;
                float v0 = acc[mt][nt][half*2 + 0];
                float v1 = acc[mt][nt][half*2 + 1];
                if (EPI == EPI_QKV) {
                    int bb = m >> 11, tt = m & 2047;
                    int t = col >> 10, nn = col & 1023, h = nn >> 6, d0 = nn & 63;
                    size_t o = (((size_t)(bb*HH + h)) * TT + tt) * DH + d0;
                    if (t == 2) {
                        float2 w2; w2.x = v0; w2.y = v1;
                        *(float2*)(ovv + o) = w2;
                    } else {
                        float s = (t == 0) ? 0.03125f : 1.0f;   // q pre-scaled by E^-0.5
                        bf16 h0, l0, h1, l1;
                        split_bf16(v0 * s, h0, l0);
                        split_bf16(v1 * s, h1, l1);
                        bf162 hp; hp.x = h0; hp.y = h1;
                        bf162 lp; lp.x = l0; lp.y = l1;
                        bf16* dh = (t == 0) ? oqh : okh;
                        bf16* dl = (t == 0) ? oql : okl;
                        *(bf162*)(dh + o) = hp;
                        *(bf162*)(dl + o) = lp;
                    }
                } else if (EPI == EPI_BIAS_RESID) {
                    size_t o = (size_t)m * N + col;
                    float2 r2 = *(const float2*)(resid + o);
                    float2 w2;
                    w2.x = v0 + bias[col]     + r2.x;
                    w2.y = v1 + bias[col + 1] + r2.y;
                    *(float2*)(Cf + o) = w2;
                } else { // EPI_RELU_SPLIT
                    size_t o = (size_t)m * N + col;
                    float u0 = fmaxf(v0 + bias[col],     0.f);
                    float u1 = fmaxf(v1 + bias[col + 1], 0.f);
                    bf16 h0, l0, h1, l1;
                    split_bf16(u0, h0, l0); split_bf16(u1, h1, l1);
                    bf162 hp; hp.x = h0; hp.y = h1;
                    bf162 lp; lp.x = l0; lp.y = l1;
                    *(bf162*)(Oh + o) = hp;
                    *(bf162*)(Ol + o) = lp;
                }
            }
        }
    }
}

// =============== HMMA flash attention: 128 q rows/block, 8 warps ===========
// smem: Qh 16K | Ql 16K | stage0 (Kh,Kl,Vth,Vtl 8K each) | stage1
#define FL_SMEM (32768 + 2*32768)   // 98304

__global__ void __launch_bounds__(256, 1) flash_hmma(
    const bf16* __restrict__ qh, const bf16* __restrict__ ql,
    const bf16* __restrict__ kh, const bf16* __restrict__ kl,
    const bf16* __restrict__ vth, const bf16* __restrict__ vtl,
    bf16* __restrict__ atth, bf16* __restrict__ attl)
{
    extern __shared__ char smraw[];
    uint32_t sbase = smem_to_u32(smraw);

    int tid  = threadIdx.x;
    int w    = tid >> 5, lane = tid & 31;
    int g    = lane >> 3, lr = lane & 7;
    int qb   = blockIdx.x;          // 0..15
    int bh   = blockIdx.y;          // b*16+h
    int b    = bh >> 4, h = bh & 15;

    const bf16* qhp = qh + ((size_t)bh * TT + qb*128) * DH;
    const bf16* qlp = ql + ((size_t)bh * TT + qb*128) * DH;
    const bf16* khp = kh + (size_t)bh * TT * DH;
    const bf16* klp = kl + (size_t)bh * TT * DH;
    const bf16* vhp = vth + (size_t)bh * DH * TT;
    const bf16* vlp = vtl + (size_t)bh * DH * TT;

    const int ntile = 2*qb + 2;

    // ---- initial copies: Q (both) + stage 0, one commit group ----
    {
        // Q: 128 rows x 128B, 1024 chunks each buf
        #pragma unroll
        for (int it = 0; it < 4; it++) {
            int u = tid + it * 256;
            int r = u >> 3, cc = u & 7;
            uint32_t so = SWZ128((uint32_t)(r*128 + cc*16));
            CP16(sbase + so,         qhp + (size_t)r * DH + cc*8);
            CP16(sbase + 16384 + so, qlp + (size_t)r * DH + cc*8);
        }
        // stage 0: K tile 0 + Vt tile 0
        #pragma unroll
        for (int it = 0; it < 2; it++) {
            int u = tid + it * 256;
            int r = u >> 3, cc = u & 7;
            uint32_t so = SWZ128((uint32_t)(r*128 + cc*16));
            uint32_t st = sbase + 32768;
            CP16(st + so,         khp + (size_t)r * DH + cc*8);
            CP16(st + 8192 + so,  klp + (size_t)r * DH + cc*8);
            CP16(st + 16384 + so, vhp + (size_t)r * TT + cc*8);
            CP16(st + 24576 + so, vlp + (size_t)r * TT + cc*8);
        }
    }
    CP_COMMIT();

    float O[8][4];
    #pragma unroll
    for (int j = 0; j < 8; j++)
        #pragma unroll
        for (int q = 0; q < 4; q++) O[j][q] = 0.f;
    float m0 = -FLT_MAX, m1 = -FLT_MAX, l0 = 0.f, l1 = 0.f;

    int trow0 = qb*128 + w*16 + (lane >> 2);   // token row of c0/c1
    int trow1 = trow0 + 8;                     // token row of c2/c3
    int rowmaxw = qb*128 + w*16 + 15;

    uint32_t qfh[4][4], qfl[4][4];

    for (int kt = 0; kt < ntile; kt++) {
        if (kt + 1 < ntile) {
            uint32_t st = sbase + 32768 + (uint32_t)((kt+1) & 1) * 32768;
            const bf16* khq = khp + (size_t)(kt+1)*64*DH;
            const bf16* klq = klp + (size_t)(kt+1)*64*DH;
            const bf16* vhq = vhp + (size_t)(kt+1)*64;
            const bf16* vlq = vlp + (size_t)(kt+1)*64;
            #pragma unroll
            for (int it = 0; it < 2; it++) {
                int u = tid + it * 256;
                int r = u >> 3, cc = u & 7;
                uint32_t so = SWZ128((uint32_t)(r*128 + cc*16));
                CP16(st + so,         khq + (size_t)r * DH + cc*8);
                CP16(st + 8192 + so,  klq + (size_t)r * DH + cc*8);
                CP16(st + 16384 + so, vhq + (size_t)r * TT + cc*8);
                CP16(st + 24576 + so, vlq + (size_t)r * TT + cc*8);
            }
            CP_COMMIT();
            CP_WAIT(1);
        } else {
            CP_WAIT(0);
        }
        __syncthreads();

        if (kt == 0) {
            // load Q fragments once
            #pragma unroll
            for (int c = 0; c < 4; c++) {
                uint32_t off = SWZ128((uint32_t)(
                    (w*16 + (g & 1)*8 + lr) * 128 + c*32 + (g >> 1)*16));
                ldsm_x4(sbase + off,         qfh[c][0], qfh[c][1], qfh[c][2], qfh[c][3]);
                ldsm_x4(sbase + 16384 + off, qfl[c][0], qfl[c][1], qfl[c][2], qfl[c][3]);
            }
        }

        bool active = (kt*64 <= rowmaxw);
        if (active) {
            uint32_t st = sbase + 32768 + (uint32_t)(kt & 1) * 32768;
            uint32_t kH = st, kL = st + 8192, vH = st + 16384, vL = st + 24576;

            // ---- S = Qh*Kh + Qh*Kl + Ql*Kh ----
            float S[8][4];
            #pragma unroll
            for (int j = 0; j < 8; j++)
                #pragma unroll
                for (int q = 0; q < 4; q++) S[j][q] = 0.f;
            #pragma unroll
            for (int c = 0; c < 4; c++) {
                #pragma unroll
                for (int p = 0; p < 4; p++) {
                    uint32_t off = SWZ128((uint32_t)(
                        (p*16 + (g >> 1)*8 + lr) * 128 + c*32 + (g & 1)*16));
                    uint32_t bh0[2], bh1[2], bl0[2], bl1[2];
                    uint32_t r0, r1, r2, r3;
                    ldsm_x4(kH + off, r0, r1, r2, r3);
                    bh0[0]=r0; bh0[1]=r1; bh1[0]=r2; bh1[1]=r3;
                    ldsm_x4(kL + off, r0, r1, r2, r3);
                    bl0[0]=r0; bl0[1]=r1; bl1[0]=r2; bl1[1]=r3;
                    mma_bf16(S[p*2],   qfh[c], bh0);
                    mma_bf16(S[p*2],   qfh[c], bl0);
                    mma_bf16(S[p*2],   qfl[c], bh0);
                    mma_bf16(S[p*2+1], qfh[c], bh1);
                    mma_bf16(S[p*2+1], qfh[c], bl1);
                    mma_bf16(S[p*2+1], qfl[c], bh1);
                }
            }

            // ---- causal mask ----
            if (kt*64 + 63 > trow0) {
                #pragma unroll
                for (int j = 0; j < 8; j++) {
                    int c0 = kt*64 + j*8 + (lane & 3)*2;
                    if (c0     > trow0) S[j][0] = -FLT_MAX;
                    if (c0 + 1 > trow0) S[j][1] = -FLT_MAX;
                    if (c0     > trow1) S[j][2] = -FLT_MAX;
                    if (c0 + 1 > trow1) S[j][3] = -FLT_MAX;
                }
            }

            // ---- online softmax ----
            float mx0 = -FLT_MAX, mx1 = -FLT_MAX;
            #pragma unroll
            for (int j = 0; j < 8; j++) {
                mx0 = fmaxf(mx0, fmaxf(S[j][0], S[j][1]));
                mx1 = fmaxf(mx1, fmaxf(S[j][2], S[j][3]));
            }
            mx0 = fmaxf(mx0, __shfl_xor_sync(0xffffffffu, mx0, 1));
            mx0 = fmaxf(mx0, __shfl_xor_sync(0xffffffffu, mx0, 2));
            mx1 = fmaxf(mx1, __shfl_xor_sync(0xffffffffu, mx1, 1));
            mx1 = fmaxf(mx1, __shfl_xor_sync(0xffffffffu, mx1, 2));
            float mn0 = fmaxf(m0, mx0), mn1 = fmaxf(m1, mx1);
            float al0 = __expf(m0 - mn0), al1 = __expf(m1 - mn1);
            float rs0 = 0.f, rs1 = 0.f;
            #pragma unroll
            for (int j = 0; j < 8; j++) {
                S[j][0] = __expf(S[j][0] - mn0);
                S[j][1] = __expf(S[j][1] - mn0);
                S[j][2] = __expf(S[j][2] - mn1);
                S[j][3] = __expf(S[j][3] - mn1);
                rs0 += S[j][0] + S[j][1];
                rs1 += S[j][2] + S[j][3];
            }
            rs0 += __shfl_xor_sync(0xffffffffu, rs0, 1);
            rs0 += __shfl_xor_sync(0xffffffffu, rs0, 2);
            rs1 += __shfl_xor_sync(0xffffffffu, rs1, 1);
            rs1 += __shfl_xor_sync(0xffffffffu, rs1, 2);
            l0 = l0 * al0 + rs0;  m0 = mn0;
            l1 = l1 * al1 + rs1;  m1 = mn1;
            #pragma unroll
            for (int j = 0; j < 8; j++) {
                O[j][0] *= al0; O[j][1] *= al0;
                O[j][2] *= al1; O[j][3] *= al1;
            }

            // ---- O += Ph*Vh + Pl*Vh + Ph*Vl ----
            #pragma unroll
            for (int c = 0; c < 4; c++) {
                uint32_t ah[4], al_[4];
                split_pack2(S[2*c][0],   S[2*c][1],   ah[0], al_[0]);
                split_pack2(S[2*c][2],   S[2*c][3],   ah[1], al_[1]);
                split_pack2(S[2*c+1][0], S[2*c+1][1], ah[2], al_[2]);
                split_pack2(S[2*c+1][2], S[2*c+1][3], ah[3], al_[3]);
                #pragma unroll
                for (int p = 0; p < 4; p++) {
                    uint32_t off = SWZ128((uint32_t)(
                        (p*16 + (g >> 1)*8 + lr) * 128 + c*32 + (g & 1)*16));
                    uint32_t bh0[2], bh1[2], bl0[2], bl1[2];
                    uint32_t r0, r1, r2, r3;
                    ldsm_x4(vH + off, r0, r1, r2, r3);
                    bh0[0]=r0; bh0[1]=r1; bh1[0]=r2; bh1[1]=r3;
                    ldsm_x4(vL + off, r0, r1, r2, r3);
                    bl0[0]=r0; bl0[1]=r1; bl1[0]=r2; bl1[1]=r3;
                    mma_bf16(O[p*2],   ah,  bh0);
                    mma_bf16(O[p*2],   al_, bh0);
                    mma_bf16(O[p*2],   ah,  bl0);
                    mma_bf16(O[p*2+1], ah,  bh1);
                    mma_bf16(O[p*2+1], al_, bh1);
                    mma_bf16(O[p*2+1], ah,  bl1);
                }
            }
        }
        __syncthreads();
    }

    // ---- normalize + store att hi/lo [B,T,E] ----
    float il0 = 1.0f / l0, il1 = 1.0f / l1;
    #pragma unroll
    for (int j = 0; j < 8; j++) {
        int col = h*64 + j*8 + (lane & 3)*2;
        float o0 = O[j][0]*il0, o1 = O[j][1]*il0;
        float o2 = O[j][2]*il1, o3 = O[j][3]*il1;
        bf16 h0,l0b,h1,l1b,h2,l2b,h3,l3b;
        split_bf16(o0,h0,l0b); split_bf16(o1,h1,l1b);
        split_bf16(o2,h2,l2b); split_bf16(o3,h3,l3b);
        size_t o_0 = ((size_t)b*TT + trow0) * EE + col;
        size_t o_1 = ((size_t)b*TT + trow1) * EE + col;
        bf162 hp0; hp0.x=h0; hp0.y=h1;  bf162 lp0; lp0.x=l0b; lp0.y=l1b;
        bf162 hp1; hp1.x=h2; hp1.y=h3;  bf162 lp1; lp1.x=l2b; lp1.y=l3b;
        *(bf162*)(atth + o_0) = hp0;  *(bf162*)(attl + o_0) = lp0;
        *(bf162*)(atth + o_1) = hp1;  *(bf162*)(attl + o_1) = lp1;
    }
}

// ============================== launch =====================================
extern "C" void kernel_launch(void* const* d_in, const int* in_sizes, int n_in,
                              void* d_out, int out_size)
{
    const float* x     = (const float*)d_in[0];
    const float* ln1_g = (const float*)d_in[1];
    const float* ln1_b = (const float*)d_in[2];
    const float* Wq    = (const float*)d_in[3];
    const float* Wk    = (const float*)d_in[4];
    const float* Wv    = (const float*)d_in[5];
    const float* Wp    = (const float*)d_in[6];
    const float* bp    = (const float*)d_in[7];
    const float* ln2_g = (const float*)d_in[8];
    const float* ln2_b = (const float*)d_in[9];
    const float* W1    = (const float*)d_in[10];
    const float* b1    = (const float*)d_in[11];
    const float* W2    = (const float*)d_in[12];
    const float* b2    = (const float*)d_in[13];
    float* out = (float*)d_out;

    float *x1, *wqkv, *v;
    bf16 *qh_, *ql_, *kh_, *kl_, *vth_, *vtl_;
    bf16 *hh, *hl, *atth, *attl, *ffhh, *ffhl;
    bf16 *wqTh, *wqTl, *WpTh, *WpTl, *W1Th, *W1Tl, *W2Th, *W2Tl;
    cudaGetSymbolAddress((void**)&x1,   g_x1);
    cudaGetSymbolAddress((void**)&wqkv, g_wqkv);
    cudaGetSymbolAddress((void**)&v,    g_v);
    cudaGetSymbolAddress((void**)&qh_,  g_qh);
    cudaGetSymbolAddress((void**)&ql_,  g_ql);
    cudaGetSymbolAddress((void**)&kh_,  g_kh);
    cudaGetSymbolAddress((void**)&kl_,  g_kl);
    cudaGetSymbolAddress((void**)&vth_, g_vth);
    cudaGetSymbolAddress((void**)&vtl_, g_vtl);
    cudaGetSymbolAddress((void**)&hh,   g_hh);
    cudaGetSymbolAddress((void**)&hl,   g_hl);
    cudaGetSymbolAddress((void**)&atth, g_atth);
    cudaGetSymbolAddress((void**)&attl, g_attl);
    cudaGetSymbolAddress((void**)&ffhh, g_ffhh);
    cudaGetSymbolAddress((void**)&ffhl, g_ffhl);
    cudaGetSymbolAddress((void**)&wqTh, g_wqkvTh);
    cudaGetSymbolAddress((void**)&wqTl, g_wqkvTl);
    cudaGetSymbolAddress((void**)&WpTh, g_WpTh);
    cudaGetSymbolAddress((void**)&WpTl, g_WpTl);
    cudaGetSymbolAddress((void**)&W1Th, g_W1Th);
    cudaGetSymbolAddress((void**)&W1Tl, g_W1Tl);
    cudaGetSymbolAddress((void**)&W2Th, g_W2Th);
    cudaGetSymbolAddress((void**)&W2Tl, g_W2Tl);

    cudaFuncSetAttribute(flash_hmma, cudaFuncAttributeMaxDynamicSharedMemorySize, FL_SMEM);
    cudaFuncSetAttribute(gemm_tc<EPI_QKV>,        cudaFuncAttributeMaxDynamicSharedMemorySize, SMEM_GEMM);
    cudaFuncSetAttribute(gemm_tc<EPI_BIAS_RESID>, cudaFuncAttributeMaxDynamicSharedMemorySize, SMEM_GEMM);
    cudaFuncSetAttribute(gemm_tc<EPI_RELU_SPLIT>, cudaFuncAttributeMaxDynamicSharedMemorySize, SMEM_GEMM);

    // weight prep
    pack_qkv_kernel<<<(3*1024*1024)/256, 256>>>(Wq, Wk, Wv, wqkv);
    convt_kernel<<<dim3(3072/32, 1024/32), 256>>>(wqkv, wqTh, wqTl, 1024, 3072);
    convt_kernel<<<dim3(1024/32, 1024/32), 256>>>(Wp, WpTh, WpTl, 1024, 1024);
    convt_kernel<<<dim3(4096/32, 1024/32), 256>>>(W1, W1Th, W1Tl, 1024, 4096);
    convt_kernel<<<dim3(1024/32, 4096/32), 256>>>(W2, W2Th, W2Tl, 4096, 1024);

    // 1. LN1 -> hi/lo
    ln_kernel<<<MROWS, 256>>>(x, ln1_g, ln1_b, hh, hl);
    // 2. QKV projection (HMMA) -> q/k hi-lo bf16 (q pre-scaled), v fp32
    gemm_tc<EPI_QKV><<<dim3(3072/128, MROWS/128), 256, SMEM_GEMM>>>(
        hh, hl, wqTh, wqTl, 1024, 3072, nullptr, nullptr,
        nullptr, nullptr, nullptr, qh_, ql_, kh_, kl_, v);
    // 2b. V transpose -> vt hi/lo [BH, D, T]
    vt_kernel<<<dim3(TT/32, DH/32, BB*HH), 256>>>(v, vth_, vtl_);
    // 3. HMMA flash attention -> att hi/lo
    flash_hmma<<<dim3(TT/128, BB*HH), 256, FL_SMEM>>>(
        qh_, ql_, kh_, kl_, vth_, vtl_, atth, attl);
    // 4. out-proj + bias + residual -> x1
    gemm_tc<EPI_BIAS_RESID><<<dim3(1024/128, MROWS/128), 256, SMEM_GEMM>>>(
        atth, attl, WpTh, WpTl, 1024, 1024, bp, x,
        x1, nullptr, nullptr, nullptr, nullptr, nullptr, nullptr, nullptr);
    // 5. LN2 -> hi/lo
    ln_kernel<<<MROWS, 256>>>(x1, ln2_g, ln2_b, hh, hl);
    // 6. FFN up + relu -> ffh hi/lo
    gemm_tc<EPI_RELU_SPLIT><<<dim3(4096/128, MROWS/128), 256, SMEM_GEMM>>>(
        hh, hl, W1Th, W1Tl, 1024, 4096, b1, nullptr,
        nullptr, ffhh, ffhl, nullptr, nullptr, nullptr, nullptr, nullptr);
    // 7. FFN down + bias + residual -> out
    gemm_tc<EPI_BIAS_RESID><<<dim3(1024/128, MROWS/128), 256, SMEM_GEMM>>>(
        ffhh, ffhl, W2Th, W2Tl, 4096, 1024, b2, x1,
        out, nullptr, nullptr, nullptr, nullptr, nullptr, nullptr, nullptr);
}

// round 5
// speedup vs baseline: 4.6102x; 1.4427x over previous
#include <cuda_runtime.h>
#include <cuda_fp16.h>
#include <cfloat>
#include <cstdint>
#include <math.h>

#define BB 4
#define TT 2048
#define EE 1024
#define HH 16
#define DH 64
#define MROWS (BB*TT)        // 8192

typedef __half  f16;
typedef __half2 f162;

// ============================ scratch =====================================
__device__ float g_x1  [(size_t)MROWS*EE];
__device__ float g_wqkv[(size_t)EE*3072];
__device__ float g_v   [(size_t)BB*HH*TT*DH];
__device__ f16  g_qh  [(size_t)BB*HH*TT*DH];
__device__ f16  g_kh  [(size_t)BB*HH*TT*DH];
__device__ f16  g_vth [(size_t)BB*HH*DH*TT];
__device__ f16  g_hh  [(size_t)MROWS*EE];
__device__ f16  g_hl  [(size_t)MROWS*EE];
__device__ f16  g_atth[(size_t)MROWS*EE];
__device__ f16  g_attl[(size_t)MROWS*EE];
__device__ f16  g_ffhh[(size_t)MROWS*4096];
__device__ f16  g_ffhl[(size_t)MROWS*4096];
__device__ f16  g_wqkvT[(size_t)3072*EE];
__device__ f16  g_WpT[(size_t)EE*EE];
__device__ f16  g_W1T[(size_t)4096*EE];
__device__ f16  g_W2T[(size_t)EE*4096];

// ============================ helpers =====================================
__device__ __forceinline__ uint32_t smem_to_u32(const void* p) {
    uint32_t a;
    asm("{ .reg .u64 t; cvta.to.shared.u64 t, %1; cvt.u32.u64 %0, t; }"
        : "=r"(a) : "l"(p));
    return a;
}

#define SWZ128(o) ((o) ^ (((o) >> 3) & 0x70))

#define CP16(dst, src) \
    asm volatile("cp.async.cg.shared.global [%0], [%1], 16;" \
        :: "r"(dst), "l"(src) : "memory")
#define CP_COMMIT() asm volatile("cp.async.commit_group;" ::: "memory")
#define CP_WAIT(N)  asm volatile("cp.async.wait_group %0;" :: "n"(N) : "memory")

__device__ __forceinline__ void ldsm_x4(uint32_t addr,
    uint32_t& r0, uint32_t& r1, uint32_t& r2, uint32_t& r3) {
    asm volatile("ldmatrix.sync.aligned.m8n8.x4.shared.b16 {%0,%1,%2,%3}, [%4];"
        : "=r"(r0), "=r"(r1), "=r"(r2), "=r"(r3) : "r"(addr));
}

__device__ __forceinline__ void mma_f16(float* c, const uint32_t* a, const uint32_t* b) {
    asm volatile(
        "mma.sync.aligned.m16n8k16.row.col.f32.f16.f16.f32 "
        "{%0,%1,%2,%3}, {%4,%5,%6,%7}, {%8,%9}, {%0,%1,%2,%3};"
        : "+f"(c[0]), "+f"(c[1]), "+f"(c[2]), "+f"(c[3])
        : "r"(a[0]), "r"(a[1]), "r"(a[2]), "r"(a[3]), "r"(b[0]), "r"(b[1]));
}

__device__ __forceinline__ void split_f16(float x, f16& h, f16& l) {
    h = __float2half_rn(x);
    l = __float2half_rn(x - __half2float(h));
}
__device__ __forceinline__ uint32_t packh2(f16 a, f16 b) {
    f162 t = __halves2half2(a, b);
    return *reinterpret_cast<uint32_t*>(&t);
}

// ============================ LayerNorm (emits hi/lo fp16) =================
__global__ void __launch_bounds__(256) ln_kernel(
    const float* __restrict__ x, const float* __restrict__ g,
    const float* __restrict__ b, f16* __restrict__ oh, f16* __restrict__ ol)
{
    int row = blockIdx.x;
    int tid = threadIdx.x;
    float4 xv = ((const float4*)(x + (size_t)row * EE))[tid];
    float s  = xv.x + xv.y + xv.z + xv.w;
    float s2 = xv.x*xv.x + xv.y*xv.y + xv.z*xv.z + xv.w*xv.w;
    #pragma unroll
    for (int o = 16; o > 0; o >>= 1) {
        s  += __shfl_xor_sync(0xffffffffu, s,  o);
        s2 += __shfl_xor_sync(0xffffffffu, s2, o);
    }
    __shared__ float rs[8], rs2[8];
    int w = tid >> 5;
    if ((tid & 31) == 0) { rs[w] = s; rs2[w] = s2; }
    __syncthreads();
    s = 0.f; s2 = 0.f;
    #pragma unroll
    for (int i = 0; i < 8; i++) { s += rs[i]; s2 += rs2[i]; }
    float mean = s * (1.0f/1024.0f);
    float var  = s2 * (1.0f/1024.0f) - mean*mean;
    float inv  = rsqrtf(var + 1e-5f);
    float4 gv = ((const float4*)g)[tid];
    float4 bv = ((const float4*)b)[tid];
    float o0 = (xv.x - mean)*inv*gv.x + bv.x;
    float o1 = (xv.y - mean)*inv*gv.y + bv.y;
    float o2 = (xv.z - mean)*inv*gv.z + bv.z;
    float o3 = (xv.w - mean)*inv*gv.w + bv.w;
    f16 h0,l0,h1,l1,h2,l2,h3,l3;
    split_f16(o0,h0,l0); split_f16(o1,h1,l1);
    split_f16(o2,h2,l2); split_f16(o3,h3,l3);
    size_t base = (size_t)row * EE + tid*4;
    *(f162*)(oh+base)   = __halves2half2(h0,h1);
    *(f162*)(oh+base+2) = __halves2half2(h2,h3);
    *(f162*)(ol+base)   = __halves2half2(l0,l1);
    *(f162*)(ol+base+2) = __halves2half2(l2,l3);
}

// ============== pack Wq/Wk/Wv -> fp32 [E rows, 3072 cols] ==================
__global__ void pack_qkv_kernel(const float* __restrict__ Wq,
                                const float* __restrict__ Wk,
                                const float* __restrict__ Wv,
                                float* __restrict__ Wpk)
{
    int i = blockIdx.x * 256 + threadIdx.x;
    int e  = i / 3072;
    int n  = i % 3072;
    int t  = n >> 10;
    int nn = n & 1023;
    int h  = nn >> 6;
    int d  = nn & 63;
    const float* W = (t == 0) ? Wq : (t == 1) ? Wk : Wv;
    Wpk[i] = W[(size_t)h * EE * DH + (size_t)e * DH + d];
}

// ====== transpose + round: src fp32 [K,N] -> dst fp16 [N,K] ================
__global__ void __launch_bounds__(256) convt_kernel(
    const float* __restrict__ src, f16* __restrict__ dh, int K, int N)
{
    __shared__ float t[32][33];
    int x = threadIdx.x & 31, y = threadIdx.x >> 5;
    int n0 = blockIdx.x * 32, k0 = blockIdx.y * 32;
    #pragma unroll
    for (int i = 0; i < 32; i += 8)
        t[y+i][x] = src[(size_t)(k0 + y + i) * N + n0 + x];
    __syncthreads();
    #pragma unroll
    for (int i = 0; i < 32; i += 8) {
        float vv = t[x][y+i];
        dh[(size_t)(n0 + y + i) * K + k0 + x] = __float2half_rn(vv);
    }
}

// ===== V transpose: v fp32 [BH, T, DH] -> vth fp16 [BH, DH, T] =============
__global__ void __launch_bounds__(256) vt_kernel(
    const float* __restrict__ v, f16* __restrict__ vth)
{
    __shared__ float t[32][33];
    int x = threadIdx.x & 31, y = threadIdx.x >> 5;
    int bh = blockIdx.z;
    int t0 = blockIdx.x * 32, d0 = blockIdx.y * 32;
    const float* src = v + (size_t)bh * TT * DH;
    #pragma unroll
    for (int i = 0; i < 32; i += 8)
        t[y+i][x] = src[(size_t)(t0 + y + i) * DH + d0 + x];
    __syncthreads();
    #pragma unroll
    for (int i = 0; i < 32; i += 8) {
        float vv = t[x][y+i];   // = v[t0+x][d0+y+i]
        vth[((size_t)bh * DH + d0 + y + i) * TT + t0 + x] = __float2half_rn(vv);
    }
}

// ===== HMMA GEMM: C[M,N] = (Ah+Al)[M,K] * B[N,K]^T, fp16, 3-stage ==========
enum { EPI_QKV = 0, EPI_BIAS_RESID = 1, EPI_RELU_SPLIT = 2 };

#define KCHUNK 64
#define TILE_BYTES 16384                  // 128 rows x 64 fp16
#define STAGE_BYTES (3*TILE_BYTES)        // Ah Al Bh = 49152
#define SMEM_GEMM (3*STAGE_BYTES + 1024)  // 148480

template<int EPI>
__global__ void __launch_bounds__(256, 1) gemm_tc(
    const f16* __restrict__ Ah, const f16* __restrict__ Al,
    const f16* __restrict__ Bh,
    int K, int N,
    const float* __restrict__ bias, const float* __restrict__ resid,
    float* __restrict__ Cf, f16* __restrict__ Oh, f16* __restrict__ Ol,
    f16* __restrict__ oqh, f16* __restrict__ okh, float* __restrict__ ovv)
{
    extern __shared__ char smraw[];
    uint32_t raw = smem_to_u32(smraw);
    uint32_t sbase = (raw + 1023u) & ~1023u;

    int tid  = threadIdx.x;
    int wid  = tid >> 5, lane = tid & 31;
    int m0 = blockIdx.y * 128;
    int n0 = blockIdx.x * 128;
    int mw = (wid & 1) * 64;       // warp row offset
    int nw = (wid >> 1) * 32;      // warp col offset

    const f16* gptr[3];
    gptr[0] = Ah + (size_t)m0 * K;
    gptr[1] = Al + (size_t)m0 * K;
    gptr[2] = Bh + (size_t)n0 * K;

    const int nk = K / KCHUNK;

    auto prefetch = [&](int c) {
        uint32_t st = sbase + (uint32_t)(c % 3) * STAGE_BYTES;
        int kc = c * KCHUNK;
        #pragma unroll
        for (int t = 0; t < 3; t++) {
            #pragma unroll
            for (int it = 0; it < 4; it++) {
                int u = tid + it * 256;           // 1024 16B-units per tile
                int r = u >> 3, cc = u & 7;
                uint32_t so = st + (uint32_t)t * TILE_BYTES
                            + SWZ128((uint32_t)(r * 128 + cc * 16));
                CP16(so, gptr[t] + (size_t)r * K + kc + cc * 8);
            }
        }
    };

    float acc[4][4][4];
    #pragma unroll
    for (int mt = 0; mt < 4; mt++)
        #pragma unroll
        for (int nt = 0; nt < 4; nt++)
            #pragma unroll
            for (int q = 0; q < 4; q++) acc[mt][nt][q] = 0.f;

    prefetch(0); CP_COMMIT();
    if (nk > 1) { prefetch(1); CP_COMMIT(); }

    int g  = lane >> 3;   // ldmatrix lane group
    int lr = lane & 7;

    for (int c = 0; c < nk; c++) {
        if (c + 2 < nk) { prefetch(c + 2); CP_COMMIT(); CP_WAIT(2); }
        else if (c + 1 < nk) { CP_WAIT(1); }
        else { CP_WAIT(0); }
        __syncthreads();

        uint32_t st = sbase + (uint32_t)(c % 3) * STAGE_BYTES;
        uint32_t aH = st, aL = st + TILE_BYTES, bH = st + 2*TILE_BYTES;

        #pragma unroll
        for (int ks = 0; ks < 4; ks++) {
            uint32_t ah[4][4], al[4][4], bh[4][2];
            #pragma unroll
            for (int mt = 0; mt < 4; mt++) {
                uint32_t off = SWZ128((uint32_t)(
                    (mw + mt*16 + (g & 1)*8 + lr) * 128 + ks*32 + (g >> 1)*16));
                ldsm_x4(aH + off, ah[mt][0], ah[mt][1], ah[mt][2], ah[mt][3]);
                ldsm_x4(aL + off, al[mt][0], al[mt][1], al[mt][2], al[mt][3]);
            }
            #pragma unroll
            for (int p = 0; p < 2; p++) {
                uint32_t off = SWZ128((uint32_t)(
                    (nw + p*16 + (g >> 1)*8 + lr) * 128 + ks*32 + (g & 1)*16));
                uint32_t r0, r1, r2, r3;
                ldsm_x4(bH + off, r0, r1, r2, r3);
                bh[p*2][0] = r0; bh[p*2][1] = r1;
                bh[p*2+1][0] = r2; bh[p*2+1][1] = r3;
            }
            #pragma unroll
            for (int mt = 0; mt < 4; mt++)
                #pragma unroll
                for (int nt = 0; nt < 4; nt++) {
                    mma_f16(acc[mt][nt], ah[mt], bh[nt]);
                    mma_f16(acc[mt][nt], al[mt], bh[nt]);
                }
        }
        __syncthreads();
    }

    // ------------------------------ epilogue -------------------------------
    int qr = lane >> 2;        // 0..7
    int qc = (lane & 3) * 2;   // 0,2,4,6
    #pragma unroll
    for (int mt = 0; mt < 4; mt++) {
        #pragma unroll
        for (int nt = 0; nt < 4; nt++) {
            int col = n0 + nw + nt*8 + qc;
            #pragma unroll
            for (int half = 0; half < 2; half++) {
                int m = m0 + mw + mt*16 + qr + half*8;
                float v0 = acc[mt][nt][half*2 + 0];
                float v1 = acc[mt][nt][half*2 + 1];
                if (EPI == EPI_QKV) {
                    int bb = m >> 11, tt = m & 2047;
                    int t = col >> 10, nn = col & 1023, h = nn >> 6, d0 = nn & 63;
                    size_t o = (((size_t)(bb*HH + h)) * TT + tt) * DH + d0;
                    if (t == 2) {
                        float2 w2; w2.x = v0; w2.y = v1;
                        *(float2*)(ovv + o) = w2;
                    } else {
                        float s = (t == 0) ? 0.03125f : 1.0f;   // q pre-scaled E^-0.5
                        f16* dst = (t == 0) ? oqh : okh;
                        *(f162*)(dst + o) = __halves2half2(
                            __float2half_rn(v0 * s), __float2half_rn(v1 * s));
                    }
                } else if (EPI == EPI_BIAS_RESID) {
                    size_t o = (size_t)m * N + col;
                    float2 r2 = *(const float2*)(resid + o);
                    float2 w2;
                    w2.x = v0 + bias[col]     + r2.x;
                    w2.y = v1 + bias[col + 1] + r2.y;
                    *(float2*)(Cf + o) = w2;
                } else { // EPI_RELU_SPLIT
                    size_t o = (size_t)m * N + col;
                    float u0 = fmaxf(v0 + bias[col],     0.f);
                    float u1 = fmaxf(v1 + bias[col + 1], 0.f);
                    f16 h0, l0, h1, l1;
                    split_f16(u0, h0, l0); split_f16(u1, h1, l1);
                    *(f162*)(Oh + o) = __halves2half2(h0, h1);
                    *(f162*)(Ol + o) = __halves2half2(l0, l1);
                }
            }
        }
    }
}

// =============== HMMA flash attention: fp16 single-stream ==================
// smem: Q 16K | stage0 (Kh 8K, Vth 8K) | stage1
#define FL_SMEM (16384 + 2*16384)   // 49152

__global__ void __launch_bounds__(256) flash_hmma(
    const f16* __restrict__ qh, const f16* __restrict__ kh,
    const f16* __restrict__ vth,
    f16* __restrict__ atth, f16* __restrict__ attl)
{
    extern __shared__ char smraw[];
    uint32_t sbase = smem_to_u32(smraw);

    int tid  = threadIdx.x;
    int w    = tid >> 5, lane = tid & 31;
    int g    = lane >> 3, lr = lane & 7;
    int qb   = blockIdx.x;          // 0..15
    int bh   = blockIdx.y;          // b*16+h
    int b    = bh >> 4, h = bh & 15;

    const f16* qp  = qh + ((size_t)bh * TT + qb*128) * DH;
    const f16* kp  = kh + (size_t)bh * TT * DH;
    const f16* vp  = vth + (size_t)bh * DH * TT;

    const int ntile = 2*qb + 2;

    // ---- initial copies: Q + stage 0, one commit group ----
    {
        #pragma unroll
        for (int it = 0; it < 4; it++) {
            int u = tid + it * 256;
            int r = u >> 3, cc = u & 7;
            uint32_t so = SWZ128((uint32_t)(r*128 + cc*16));
            CP16(sbase + so, qp + (size_t)r * DH + cc*8);
        }
        #pragma unroll
        for (int it = 0; it < 2; it++) {
            int u = tid + it * 256;     // 512 units: 64 rows x 8
            int r = u >> 3, cc = u & 7;
            uint32_t so = SWZ128((uint32_t)(r*128 + cc*16));
            uint32_t st = sbase + 16384;
            CP16(st + so,        kp + (size_t)r * DH + cc*8);
            CP16(st + 8192 + so, vp + (size_t)r * TT + cc*8);
        }
    }
    CP_COMMIT();

    float O[8][4];
    #pragma unroll
    for (int j = 0; j < 8; j++)
        #pragma unroll
        for (int q = 0; q < 4; q++) O[j][q] = 0.f;
    float m0 = -FLT_MAX, m1 = -FLT_MAX, l0 = 0.f, l1 = 0.f;

    int trow0 = qb*128 + w*16 + (lane >> 2);   // token row of c0/c1
    int trow1 = trow0 + 8;                     // token row of c2/c3
    int rowmaxw = qb*128 + w*16 + 15;

    uint32_t qf[4][4];

    for (int kt = 0; kt < ntile; kt++) {
        if (kt + 1 < ntile) {
            uint32_t st = sbase + 16384 + (uint32_t)((kt+1) & 1) * 16384;
            const f16* kq = kp + (size_t)(kt+1)*64*DH;
            const f16* vq = vp + (size_t)(kt+1)*64;
            #pragma unroll
            for (int it = 0; it < 2; it++) {
                int u = tid + it * 256;
                int r = u >> 3, cc = u & 7;
                uint32_t so = SWZ128((uint32_t)(r*128 + cc*16));
                CP16(st + so,        kq + (size_t)r * DH + cc*8);
                CP16(st + 8192 + so, vq + (size_t)r * TT + cc*8);
            }
            CP_COMMIT();
            CP_WAIT(1);
        } else {
            CP_WAIT(0);
        }
        __syncthreads();

        if (kt == 0) {
            #pragma unroll
            for (int c = 0; c < 4; c++) {
                uint32_t off = SWZ128((uint32_t)(
                    (w*16 + (g & 1)*8 + lr) * 128 + c*32 + (g >> 1)*16));
                ldsm_x4(sbase + off, qf[c][0], qf[c][1], qf[c][2], qf[c][3]);
            }
        }

        bool active = (kt*64 <= rowmaxw);
        if (active) {
            uint32_t st = sbase + 16384 + (uint32_t)(kt & 1) * 16384;
            uint32_t kH = st, vH = st + 8192;

            // ---- S = Q*K^T ----
            float S[8][4];
            #pragma unroll
            for (int j = 0; j < 8; j++)
                #pragma unroll
                for (int q = 0; q < 4; q++) S[j][q] = 0.f;
            #pragma unroll
            for (int c = 0; c < 4; c++) {
                #pragma unroll
                for (int p = 0; p < 4; p++) {
                    uint32_t off = SWZ128((uint32_t)(
                        (p*16 + (g >> 1)*8 + lr) * 128 + c*32 + (g & 1)*16));
                    uint32_t r0, r1, r2, r3;
                    ldsm_x4(kH + off, r0, r1, r2, r3);
                    uint32_t b0[2] = {r0, r1}, b1[2] = {r2, r3};
                    mma_f16(S[p*2],   qf[c], b0);
                    mma_f16(S[p*2+1], qf[c], b1);
                }
            }

            // ---- causal mask ----
            if (kt*64 + 63 > trow0) {
                #pragma unroll
                for (int j = 0; j < 8; j++) {
                    int c0 = kt*64 + j*8 + (lane & 3)*2;
                    if (c0     > trow0) S[j][0] = -FLT_MAX;
                    if (c0 + 1 > trow0) S[j][1] = -FLT_MAX;
                    if (c0     > trow1) S[j][2] = -FLT_MAX;
                    if (c0 + 1 > trow1) S[j][3] = -FLT_MAX;
                }
            }

            // ---- online softmax ----
            float mx0 = -FLT_MAX, mx1 = -FLT_MAX;
            #pragma unroll
            for (int j = 0; j < 8; j++) {
                mx0 = fmaxf(mx0, fmaxf(S[j][0], S[j][1]));
                mx1 = fmaxf(mx1, fmaxf(S[j][2], S[j][3]));
            }
            mx0 = fmaxf(mx0, __shfl_xor_sync(0xffffffffu, mx0, 1));
            mx0 = fmaxf(mx0, __shfl_xor_sync(0xffffffffu, mx0, 2));
            mx1 = fmaxf(mx1, __shfl_xor_sync(0xffffffffu, mx1, 1));
            mx1 = fmaxf(mx1, __shfl_xor_sync(0xffffffffu, mx1, 2));
            float mn0 = fmaxf(m0, mx0), mn1 = fmaxf(m1, mx1);
            float al0 = __expf(m0 - mn0), al1 = __expf(m1 - mn1);
            float rs0 = 0.f, rs1 = 0.f;
            #pragma unroll
            for (int j = 0; j < 8; j++) {
                S[j][0] = __expf(S[j][0] - mn0);
                S[j][1] = __expf(S[j][1] - mn0);
                S[j][2] = __expf(S[j][2] - mn1);
                S[j][3] = __expf(S[j][3] - mn1);
                rs0 += S[j][0] + S[j][1];
                rs1 += S[j][2] + S[j][3];
            }
            rs0 += __shfl_xor_sync(0xffffffffu, rs0, 1);
            rs0 += __shfl_xor_sync(0xffffffffu, rs0, 2);
            rs1 += __shfl_xor_sync(0xffffffffu, rs1, 1);
            rs1 += __shfl_xor_sync(0xffffffffu, rs1, 2);
            l0 = l0 * al0 + rs0;  m0 = mn0;
            l1 = l1 * al1 + rs1;  m1 = mn1;
            #pragma unroll
            for (int j = 0; j < 8; j++) {
                O[j][0] *= al0; O[j][1] *= al0;
                O[j][2] *= al1; O[j][3] *= al1;
            }

            // ---- O += P*V ----
            #pragma unroll
            for (int c = 0; c < 4; c++) {
                uint32_t ph[4];
                f162 t0 = __float22half2_rn(make_float2(S[2*c][0],   S[2*c][1]));
                f162 t1 = __float22half2_rn(make_float2(S[2*c][2],   S[2*c][3]));
                f162 t2 = __float22half2_rn(make_float2(S[2*c+1][0], S[2*c+1][1]));
                f162 t3 = __float22half2_rn(make_float2(S[2*c+1][2], S[2*c+1][3]));
                ph[0] = *reinterpret_cast<uint32_t*>(&t0);
                ph[1] = *reinterpret_cast<uint32_t*>(&t1);
                ph[2] = *reinterpret_cast<uint32_t*>(&t2);
                ph[3] = *reinterpret_cast<uint32_t*>(&t3);
                #pragma unroll
                for (int p = 0; p < 4; p++) {
                    uint32_t off = SWZ128((uint32_t)(
                        (p*16 + (g >> 1)*8 + lr) * 128 + c*32 + (g & 1)*16));
                    uint32_t r0, r1, r2, r3;
                    ldsm_x4(vH + off, r0, r1, r2, r3);
                    uint32_t b0[2] = {r0, r1}, b1[2] = {r2, r3};
                    mma_f16(O[p*2],   ph, b0);
                    mma_f16(O[p*2+1], ph, b1);
                }
            }
        }
        __syncthreads();
    }

    // ---- normalize + store att hi/lo [B,T,E] ----
    float il0 = 1.0f / l0, il1 = 1.0f / l1;
    #pragma unroll
    for (int j = 0; j < 8; j++) {
        int col = h*64 + j*8 + (lane & 3)*2;
        float o0 = O[j][0]*il0, o1 = O[j][1]*il0;
        float o2 = O[j][2]*il1, o3 = O[j][3]*il1;
        f16 h0,l0b,h1,l1b,h2,l2b,h3,l3b;
        split_f16(o0,h0,l0b); split_f16(o1,h1,l1b);
        split_f16(o2,h2,l2b); split_f16(o3,h3,l3b);
        size_t o_0 = ((size_t)b*TT + trow0) * EE + col;
        size_t o_1 = ((size_t)b*TT + trow1) * EE + col;
        *(f162*)(atth + o_0) = __halves2half2(h0, h1);
        *(f162*)(attl + o_0) = __halves2half2(l0b, l1b);
        *(f162*)(atth + o_1) = __halves2half2(h2, h3);
        *(f162*)(attl + o_1) = __halves2half2(l2b, l3b);
    }
}

// ============================== launch =====================================
extern "C" void kernel_launch(void* const* d_in, const int* in_sizes, int n_in,
                              void* d_out, int out_size)
{
    const float* x     = (const float*)d_in[0];
    const float* ln1_g = (const float*)d_in[1];
    const float* ln1_b = (const float*)d_in[2];
    const float* Wq    = (const float*)d_in[3];
    const float* Wk    = (const float*)d_in[4];
    const float* Wv    = (const float*)d_in[5];
    const float* Wp    = (const float*)d_in[6];
    const float* bp    = (const float*)d_in[7];
    const float* ln2_g = (const float*)d_in[8];
    const float* ln2_b = (const float*)d_in[9];
    const float* W1    = (const float*)d_in[10];
    const float* b1    = (const float*)d_in[11];
    const float* W2    = (const float*)d_in[12];
    const float* b2    = (const float*)d_in[13];
    float* out = (float*)d_out;

    float *x1, *wqkv, *v;
    f16 *qh_, *kh_, *vth_;
    f16 *hh, *hl, *atth, *attl, *ffhh, *ffhl;
    f16 *wqT, *WpT, *W1T, *W2T;
    cudaGetSymbolAddress((void**)&x1,   g_x1);
    cudaGetSymbolAddress((void**)&wqkv, g_wqkv);
    cudaGetSymbolAddress((void**)&v,    g_v);
    cudaGetSymbolAddress((void**)&qh_,  g_qh);
    cudaGetSymbolAddress((void**)&kh_,  g_kh);
    cudaGetSymbolAddress((void**)&vth_, g_vth);
    cudaGetSymbolAddress((void**)&hh,   g_hh);
    cudaGetSymbolAddress((void**)&hl,   g_hl);
    cudaGetSymbolAddress((void**)&atth, g_atth);
    cudaGetSymbolAddress((void**)&attl, g_attl);
    cudaGetSymbolAddress((void**)&ffhh, g_ffhh);
    cudaGetSymbolAddress((void**)&ffhl, g_ffhl);
    cudaGetSymbolAddress((void**)&wqT,  g_wqkvT);
    cudaGetSymbolAddress((void**)&WpT,  g_WpT);
    cudaGetSymbolAddress((void**)&W1T,  g_W1T);
    cudaGetSymbolAddress((void**)&W2T,  g_W2T);

    cudaFuncSetAttribute(flash_hmma, cudaFuncAttributeMaxDynamicSharedMemorySize, FL_SMEM);
    cudaFuncSetAttribute(gemm_tc<EPI_QKV>,        cudaFuncAttributeMaxDynamicSharedMemorySize, SMEM_GEMM);
    cudaFuncSetAttribute(gemm_tc<EPI_BIAS_RESID>, cudaFuncAttributeMaxDynamicSharedMemorySize, SMEM_GEMM);
    cudaFuncSetAttribute(gemm_tc<EPI_RELU_SPLIT>, cudaFuncAttributeMaxDynamicSharedMemorySize, SMEM_GEMM);

    // weight prep (rounded fp16, transposed)
    pack_qkv_kernel<<<(3*1024*1024)/256, 256>>>(Wq, Wk, Wv, wqkv);
    convt_kernel<<<dim3(3072/32, 1024/32), 256>>>(wqkv, wqT, 1024, 3072);
    convt_kernel<<<dim3(1024/32, 1024/32), 256>>>(Wp, WpT, 1024, 1024);
    convt_kernel<<<dim3(4096/32, 1024/32), 256>>>(W1, W1T, 1024, 4096);
    convt_kernel<<<dim3(1024/32, 4096/32), 256>>>(W2, W2T, 4096, 1024);

    // 1. LN1 -> hi/lo fp16
    ln_kernel<<<MROWS, 256>>>(x, ln1_g, ln1_b, hh, hl);
    // 2. QKV projection -> q (scaled) / k fp16, v fp32
    gemm_tc<EPI_QKV><<<dim3(3072/128, MROWS/128), 256, SMEM_GEMM>>>(
        hh, hl, wqT, 1024, 3072, nullptr, nullptr,
        nullptr, nullptr, nullptr, qh_, kh_, v);
    // 2b. V transpose -> vt fp16 [BH, D, T]
    vt_kernel<<<dim3(TT/32, DH/32, BB*HH), 256>>>(v, vth_);
    // 3. flash attention -> att hi/lo fp16
    flash_hmma<<<dim3(TT/128, BB*HH), 256, FL_SMEM>>>(
        qh_, kh_, vth_, atth, attl);
    // 4. out-proj + bias + residual -> x1
    gemm_tc<EPI_BIAS_RESID><<<dim3(1024/128, MROWS/128), 256, SMEM_GEMM>>>(
        atth, attl, WpT, 1024, 1024, bp, x,
        x1, nullptr, nullptr, nullptr, nullptr, nullptr);
    // 5. LN2 -> hi/lo fp16
    ln_kernel<<<MROWS, 256>>>(x1, ln2_g, ln2_b, hh, hl);
    // 6. FFN up + relu -> ffh hi/lo fp16
    gemm_tc<EPI_RELU_SPLIT><<<dim3(4096/128, MROWS/128), 256, SMEM_GEMM>>>(
        hh, hl, W1T, 1024, 4096, b1, nullptr,
        nullptr, ffhh, ffhl, nullptr, nullptr, nullptr);
    // 7. FFN down + bias + residual -> out
    gemm_tc<EPI_BIAS_RESID><<<dim3(1024/128, MROWS/128), 256, SMEM_GEMM>>>(
        ffhh, ffhl, W2T, 4096, 1024, b2, x1,
        out, nullptr, nullptr, nullptr, nullptr, nullptr);
}

// round 6
// speedup vs baseline: 7.5407x; 1.6357x over previous
#include <cuda_runtime.h>
#include <cuda_fp16.h>
#include <cfloat>
#include <cstdint>
#include <math.h>

#define BB 4
#define TT 2048
#define EE 1024
#define HH 16
#define DH 64
#define MROWS (BB*TT)        // 8192

typedef __half  f16;
typedef __half2 f162;

// ============================ scratch =====================================
__device__ float g_x1 [(size_t)MROWS*EE];
__device__ f16  g_qh  [(size_t)BB*HH*TT*DH];
__device__ f16  g_kh  [(size_t)BB*HH*TT*DH];
__device__ f16  g_vh  [(size_t)BB*HH*TT*DH];
__device__ f16  g_h   [(size_t)MROWS*EE];
__device__ f16  g_att [(size_t)MROWS*EE];
__device__ f16  g_ff  [(size_t)MROWS*4096];
__device__ f16  g_wqkvT[(size_t)3072*EE];
__device__ f16  g_WpT[(size_t)EE*EE];
__device__ f16  g_W1T[(size_t)4096*EE];
__device__ f16  g_W2T[(size_t)EE*4096];

// ============================ helpers =====================================
__device__ __forceinline__ uint32_t smem_to_u32(const void* p) {
    uint32_t a;
    asm("{ .reg .u64 t; cvta.to.shared.u64 t, %1; cvt.u32.u64 %0, t; }"
        : "=r"(a) : "l"(p));
    return a;
}

#define SWZ128(o) ((o) ^ (((o) >> 3) & 0x70))

#define CP16(dst, src) \
    asm volatile("cp.async.cg.shared.global [%0], [%1], 16;" \
        :: "r"(dst), "l"(src) : "memory")
#define CP_COMMIT() asm volatile("cp.async.commit_group;" ::: "memory")
#define CP_WAIT(N)  asm volatile("cp.async.wait_group %0;" :: "n"(N) : "memory")

__device__ __forceinline__ void ldsm_x4(uint32_t addr,
    uint32_t& r0, uint32_t& r1, uint32_t& r2, uint32_t& r3) {
    asm volatile("ldmatrix.sync.aligned.m8n8.x4.shared.b16 {%0,%1,%2,%3}, [%4];"
        : "=r"(r0), "=r"(r1), "=r"(r2), "=r"(r3) : "r"(addr));
}
__device__ __forceinline__ void ldsm_x4_trans(uint32_t addr,
    uint32_t& r0, uint32_t& r1, uint32_t& r2, uint32_t& r3) {
    asm volatile("ldmatrix.sync.aligned.m8n8.x4.trans.shared.b16 {%0,%1,%2,%3}, [%4];"
        : "=r"(r0), "=r"(r1), "=r"(r2), "=r"(r3) : "r"(addr));
}

__device__ __forceinline__ void mma_f16(float* c, const uint32_t* a, const uint32_t* b) {
    asm volatile(
        "mma.sync.aligned.m16n8k16.row.col.f32.f16.f16.f32 "
        "{%0,%1,%2,%3}, {%4,%5,%6,%7}, {%8,%9}, {%0,%1,%2,%3};"
        : "+f"(c[0]), "+f"(c[1]), "+f"(c[2]), "+f"(c[3])
        : "r"(a[0]), "r"(a[1]), "r"(a[2]), "r"(a[3]), "r"(b[0]), "r"(b[1]));
}

// ============================ LayerNorm (emits fp16) =======================
__global__ void __launch_bounds__(256) ln_kernel(
    const float* __restrict__ x, const float* __restrict__ g,
    const float* __restrict__ b, f16* __restrict__ oh)
{
    int row = blockIdx.x;
    int tid = threadIdx.x;
    float4 xv = ((const float4*)(x + (size_t)row * EE))[tid];
    float s  = xv.x + xv.y + xv.z + xv.w;
    float s2 = xv.x*xv.x + xv.y*xv.y + xv.z*xv.z + xv.w*xv.w;
    #pragma unroll
    for (int o = 16; o > 0; o >>= 1) {
        s  += __shfl_xor_sync(0xffffffffu, s,  o);
        s2 += __shfl_xor_sync(0xffffffffu, s2, o);
    }
    __shared__ float rs[8], rs2[8];
    int w = tid >> 5;
    if ((tid & 31) == 0) { rs[w] = s; rs2[w] = s2; }
    __syncthreads();
    s = 0.f; s2 = 0.f;
    #pragma unroll
    for (int i = 0; i < 8; i++) { s += rs[i]; s2 += rs2[i]; }
    float mean = s * (1.0f/1024.0f);
    float var  = s2 * (1.0f/1024.0f) - mean*mean;
    float inv  = rsqrtf(var + 1e-5f);
    float4 gv = ((const float4*)g)[tid];
    float4 bv = ((const float4*)b)[tid];
    float o0 = (xv.x - mean)*inv*gv.x + bv.x;
    float o1 = (xv.y - mean)*inv*gv.y + bv.y;
    float o2 = (xv.z - mean)*inv*gv.z + bv.z;
    float o3 = (xv.w - mean)*inv*gv.w + bv.w;
    size_t base = (size_t)row * EE + tid*4;
    *(f162*)(oh+base)   = __float22half2_rn(make_float2(o0,o1));
    *(f162*)(oh+base+2) = __float22half2_rn(make_float2(o2,o3));
}

// ===== fused: Wq/Wk/Wv [H,E,DH] -> wqT fp16 [3*1024 rows, E cols] ==========
__global__ void __launch_bounds__(256) qkvw_kernel(
    const float* __restrict__ Wq, const float* __restrict__ Wk,
    const float* __restrict__ Wv, f16* __restrict__ wqT)
{
    __shared__ float t[32][33];
    int x = threadIdx.x & 31, y = threadIdx.x >> 5;
    int z = blockIdx.z;
    int tq = z >> 4, h = z & 15;
    const float* W = (tq == 0) ? Wq : (tq == 1) ? Wk : Wv;
    int e0 = blockIdx.x * 32, d0 = blockIdx.y * 32;
    #pragma unroll
    for (int i = 0; i < 32; i += 8)
        t[y+i][x] = W[(size_t)h * EE * DH + (size_t)(e0 + y + i) * DH + d0 + x];
    __syncthreads();
    #pragma unroll
    for (int i = 0; i < 32; i += 8) {
        int rown = tq*1024 + h*64 + d0 + y + i;
        wqT[(size_t)rown * EE + e0 + x] = __float2half_rn(t[x][y+i]);
    }
}

// ====== transpose + round: src fp32 [K,N] -> dst fp16 [N,K] ================
__global__ void __launch_bounds__(256) convt_kernel(
    const float* __restrict__ src, f16* __restrict__ dh, int K, int N)
{
    __shared__ float t[32][33];
    int x = threadIdx.x & 31, y = threadIdx.x >> 5;
    int n0 = blockIdx.x * 32, k0 = blockIdx.y * 32;
    #pragma unroll
    for (int i = 0; i < 32; i += 8)
        t[y+i][x] = src[(size_t)(k0 + y + i) * N + n0 + x];
    __syncthreads();
    #pragma unroll
    for (int i = 0; i < 32; i += 8) {
        float vv = t[x][y+i];
        dh[(size_t)(n0 + y + i) * K + k0 + x] = __float2half_rn(vv);
    }
}

// ===== HMMA GEMM: C[M,N] = A[M,K] * B[N,K]^T, fp16, 128x256 tile, 3-stage ==
enum { EPI_QKV = 0, EPI_BIAS_RESID = 1, EPI_RELU = 2 };

#define KCHUNK 64
#define A_TILE_BYTES 16384                // 128 rows x 64 fp16
#define B_TILE_BYTES 32768                // 256 rows x 64 fp16
#define STAGE_BYTES (A_TILE_BYTES + B_TILE_BYTES)   // 49152
#define SMEM_GEMM (3*STAGE_BYTES + 1024)            // 148480

template<int EPI>
__global__ void __launch_bounds__(256, 1) gemm_tc(
    const f16* __restrict__ A, const f16* __restrict__ B,
    int K, int N,
    const float* __restrict__ bias, const float* __restrict__ resid,
    float* __restrict__ Cf, f16* __restrict__ Of,
    f16* __restrict__ oqh, f16* __restrict__ okh, f16* __restrict__ ovh)
{
    extern __shared__ char smraw[];
    uint32_t raw = smem_to_u32(smraw);
    uint32_t sbase = (raw + 1023u) & ~1023u;

    int tid  = threadIdx.x;
    int wid  = tid >> 5, lane = tid & 31;
    int m0 = blockIdx.y * 128;
    int n0 = blockIdx.x * 256;
    int mw = (wid & 1) * 64;       // warp row offset (2 warps in M)
    int nw = (wid >> 1) * 64;      // warp col offset (4 warps in N)

    const f16* Ap = A + (size_t)m0 * K;
    const f16* Bp = B + (size_t)n0 * K;

    const int nk = K / KCHUNK;

    auto prefetch = [&](int c) {
        uint32_t st = sbase + (uint32_t)(c % 3) * STAGE_BYTES;
        int kc = c * KCHUNK;
        #pragma unroll
        for (int it = 0; it < 4; it++) {          // A: 1024 16B units
            int u = tid + it * 256;
            int r = u >> 3, cc = u & 7;
            uint32_t so = st + SWZ128((uint32_t)(r * 128 + cc * 16));
            CP16(so, Ap + (size_t)r * K + kc + cc * 8);
        }
        #pragma unroll
        for (int it = 0; it < 8; it++) {          // B: 2048 16B units
            int u = tid + it * 256;
            int r = u >> 3, cc = u & 7;
            uint32_t so = st + A_TILE_BYTES + SWZ128((uint32_t)(r * 128 + cc * 16));
            CP16(so, Bp + (size_t)r * K + kc + cc * 8);
        }
    };

    float acc[4][8][4];
    #pragma unroll
    for (int mt = 0; mt < 4; mt++)
        #pragma unroll
        for (int nt = 0; nt < 8; nt++)
            #pragma unroll
            for (int q = 0; q < 4; q++) acc[mt][nt][q] = 0.f;

    prefetch(0); CP_COMMIT();
    if (nk > 1) { prefetch(1); CP_COMMIT(); }

    int g  = lane >> 3;   // ldmatrix lane group
    int lr = lane & 7;

    for (int c = 0; c < nk; c++) {
        if (c + 2 < nk) { prefetch(c + 2); CP_COMMIT(); CP_WAIT(2); }
        else if (c + 1 < nk) { CP_WAIT(1); }
        else { CP_WAIT(0); }
        __syncthreads();

        uint32_t st = sbase + (uint32_t)(c % 3) * STAGE_BYTES;
        uint32_t aB = st, bB = st + A_TILE_BYTES;

        #pragma unroll
        for (int ks = 0; ks < 4; ks++) {
            uint32_t ah[4][4], bh[8][2];
            #pragma unroll
            for (int mt = 0; mt < 4; mt++) {
                uint32_t off = SWZ128((uint32_t)(
                    (mw + mt*16 + (g & 1)*8 + lr) * 128 + ks*32 + (g >> 1)*16));
                ldsm_x4(aB + off, ah[mt][0], ah[mt][1], ah[mt][2], ah[mt][3]);
            }
            #pragma unroll
            for (int p = 0; p < 4; p++) {
                uint32_t off = SWZ128((uint32_t)(
                    (nw + p*16 + (g >> 1)*8 + lr) * 128 + ks*32 + (g & 1)*16));
                uint32_t r0, r1, r2, r3;
                ldsm_x4(bB + off, r0, r1, r2, r3);
                bh[p*2][0] = r0; bh[p*2][1] = r1;
                bh[p*2+1][0] = r2; bh[p*2+1][1] = r3;
            }
            #pragma unroll
            for (int mt = 0; mt < 4; mt++)
                #pragma unroll
                for (int nt = 0; nt < 8; nt++)
                    mma_f16(acc[mt][nt], ah[mt], bh[nt]);
        }
        __syncthreads();
    }

    // ------------------------------ epilogue -------------------------------
    int qr = lane >> 2;        // 0..7
    int qc = (lane & 3) * 2;   // 0,2,4,6
    #pragma unroll
    for (int mt = 0; mt < 4; mt++) {
        #pragma unroll
        for (int nt = 0; nt < 8; nt++) {
            int col = n0 + nw + nt*8 + qc;
            #pragma unroll
            for (int half = 0; half < 2; half++) {
                int m = m0 + mw + mt*16 + qr + half*8;
                float v0 = acc[mt][nt][half*2 + 0];
                float v1 = acc[mt][nt][half*2 + 1];
                if (EPI == EPI_QKV) {
                    int bb = m >> 11, tt = m & 2047;
                    int t = col >> 10, nn = col & 1023, h = nn >> 6, d0 = nn & 63;
                    size_t o = (((size_t)(bb*HH + h)) * TT + tt) * DH + d0;
                    float s = (t == 0) ? 0.03125f : 1.0f;   // q pre-scaled E^-0.5
                    f16* dst = (t == 0) ? oqh : (t == 1) ? okh : ovh;
                    *(f162*)(dst + o) = __float22half2_rn(
                        make_float2(v0 * s, v1 * s));
                } else if (EPI == EPI_BIAS_RESID) {
                    size_t o = (size_t)m * N + col;
                    float2 r2 = *(const float2*)(resid + o);
                    float2 w2;
                    w2.x = v0 + bias[col]     + r2.x;
                    w2.y = v1 + bias[col + 1] + r2.y;
                    *(float2*)(Cf + o) = w2;
                } else { // EPI_RELU
                    size_t o = (size_t)m * N + col;
                    float u0 = fmaxf(v0 + bias[col],     0.f);
                    float u1 = fmaxf(v1 + bias[col + 1], 0.f);
                    *(f162*)(Of + o) = __float22half2_rn(make_float2(u0, u1));
                }
            }
        }
    }
}

// =============== HMMA flash attention: fp16, V via ldmatrix.trans ==========
// smem: Q 16K | stage0 (K 8K, V 8K) | stage1
#define FL_SMEM (16384 + 2*16384)   // 49152

__global__ void __launch_bounds__(256) flash_hmma(
    const f16* __restrict__ qh, const f16* __restrict__ kh,
    const f16* __restrict__ vh, f16* __restrict__ att)
{
    extern __shared__ char smraw[];
    uint32_t sbase = smem_to_u32(smraw);

    int tid  = threadIdx.x;
    int w    = tid >> 5, lane = tid & 31;
    int g    = lane >> 3, lr = lane & 7;
    int qb   = blockIdx.x;          // 0..15
    int bh   = blockIdx.y;          // b*16+h
    int b    = bh >> 4, h = bh & 15;

    const f16* qp = qh + ((size_t)bh * TT + qb*128) * DH;
    const f16* kp = kh + (size_t)bh * TT * DH;
    const f16* vp = vh + (size_t)bh * TT * DH;

    const int ntile = 2*qb + 2;

    // ---- initial copies: Q + stage 0 ----
    {
        #pragma unroll
        for (int it = 0; it < 4; it++) {
            int u = tid + it * 256;
            int r = u >> 3, cc = u & 7;
            uint32_t so = SWZ128((uint32_t)(r*128 + cc*16));
            CP16(sbase + so, qp + (size_t)r * DH + cc*8);
        }
        #pragma unroll
        for (int it = 0; it < 2; it++) {
            int u = tid + it * 256;     // 512 units: 64 rows x 8
            int r = u >> 3, cc = u & 7;
            uint32_t so = SWZ128((uint32_t)(r*128 + cc*16));
            uint32_t st = sbase + 16384;
            CP16(st + so,        kp + (size_t)r * DH + cc*8);
            CP16(st + 8192 + so, vp + (size_t)r * DH + cc*8);
        }
    }
    CP_COMMIT();

    float O[8][4];
    #pragma unroll
    for (int j = 0; j < 8; j++)
        #pragma unroll
        for (int q = 0; q < 4; q++) O[j][q] = 0.f;
    float m0 = -FLT_MAX, m1 = -FLT_MAX, l0 = 0.f, l1 = 0.f;

    int trow0 = qb*128 + w*16 + (lane >> 2);   // token row of c0/c1
    int trow1 = trow0 + 8;                     // token row of c2/c3
    int rowmaxw = qb*128 + w*16 + 15;

    uint32_t qf[4][4];

    for (int kt = 0; kt < ntile; kt++) {
        if (kt + 1 < ntile) {
            uint32_t st = sbase + 16384 + (uint32_t)((kt+1) & 1) * 16384;
            const f16* kq = kp + (size_t)(kt+1)*64*DH;
            const f16* vq = vp + (size_t)(kt+1)*64*DH;
            #pragma unroll
            for (int it = 0; it < 2; it++) {
                int u = tid + it * 256;
                int r = u >> 3, cc = u & 7;
                uint32_t so = SWZ128((uint32_t)(r*128 + cc*16));
                CP16(st + so,        kq + (size_t)r * DH + cc*8);
                CP16(st + 8192 + so, vq + (size_t)r * DH + cc*8);
            }
            CP_COMMIT();
            CP_WAIT(1);
        } else {
            CP_WAIT(0);
        }
        __syncthreads();

        if (kt == 0) {
            #pragma unroll
            for (int c = 0; c < 4; c++) {
                uint32_t off = SWZ128((uint32_t)(
                    (w*16 + (g & 1)*8 + lr) * 128 + c*32 + (g >> 1)*16));
                ldsm_x4(sbase + off, qf[c][0], qf[c][1], qf[c][2], qf[c][3]);
            }
        }

        bool active = (kt*64 <= rowmaxw);
        if (active) {
            uint32_t st = sbase + 16384 + (uint32_t)(kt & 1) * 16384;
            uint32_t kB = st, vB = st + 8192;

            // ---- S = Q*K^T ----
            float S[8][4];
            #pragma unroll
            for (int j = 0; j < 8; j++)
                #pragma unroll
                for (int q = 0; q < 4; q++) S[j][q] = 0.f;
            #pragma unroll
            for (int c = 0; c < 4; c++) {
                #pragma unroll
                for (int p = 0; p < 4; p++) {
                    uint32_t off = SWZ128((uint32_t)(
                        (p*16 + (g >> 1)*8 + lr) * 128 + c*32 + (g & 1)*16));
                    uint32_t r0, r1, r2, r3;
                    ldsm_x4(kB + off, r0, r1, r2, r3);
                    uint32_t b0[2] = {r0, r1}, b1[2] = {r2, r3};
                    mma_f16(S[p*2],   qf[c], b0);
                    mma_f16(S[p*2+1], qf[c], b1);
                }
            }

            // ---- causal mask ----
            if (kt*64 + 63 > trow0) {
                #pragma unroll
                for (int j = 0; j < 8; j++) {
                    int c0 = kt*64 + j*8 + (lane & 3)*2;
                    if (c0     > trow0) S[j][0] = -FLT_MAX;
                    if (c0 + 1 > trow0) S[j][1] = -FLT_MAX;
                    if (c0     > trow1) S[j][2] = -FLT_MAX;
                    if (c0 + 1 > trow1) S[j][3] = -FLT_MAX;
                }
            }

            // ---- online softmax ----
            float mx0 = -FLT_MAX, mx1 = -FLT_MAX;
            #pragma unroll
            for (int j = 0; j < 8; j++) {
                mx0 = fmaxf(mx0, fmaxf(S[j][0], S[j][1]));
                mx1 = fmaxf(mx1, fmaxf(S[j][2], S[j][3]));
            }
            mx0 = fmaxf(mx0, __shfl_xor_sync(0xffffffffu, mx0, 1));
            mx0 = fmaxf(mx0, __shfl_xor_sync(0xffffffffu, mx0, 2));
            mx1 = fmaxf(mx1, __shfl_xor_sync(0xffffffffu, mx1, 1));
            mx1 = fmaxf(mx1, __shfl_xor_sync(0xffffffffu, mx1, 2));
            float mn0 = fmaxf(m0, mx0), mn1 = fmaxf(m1, mx1);
            float al0 = __expf(m0 - mn0), al1 = __expf(m1 - mn1);
            float rs0 = 0.f, rs1 = 0.f;
            #pragma unroll
            for (int j = 0; j < 8; j++) {
                S[j][0] = __expf(S[j][0] - mn0);
                S[j][1] = __expf(S[j][1] - mn0);
                S[j][2] = __expf(S[j][2] - mn1);
                S[j][3] = __expf(S[j][3] - mn1);
                rs0 += S[j][0] + S[j][1];
                rs1 += S[j][2] + S[j][3];
            }
            rs0 += __shfl_xor_sync(0xffffffffu, rs0, 1);
            rs0 += __shfl_xor_sync(0xffffffffu, rs0, 2);
            rs1 += __shfl_xor_sync(0xffffffffu, rs1, 1);
            rs1 += __shfl_xor_sync(0xffffffffu, rs1, 2);
            l0 = l0 * al0 + rs0;  m0 = mn0;
            l1 = l1 * al1 + rs1;  m1 = mn1;
            #pragma unroll
            for (int j = 0; j < 8; j++) {
                O[j][0] *= al0; O[j][1] *= al0;
                O[j][2] *= al1; O[j][3] *= al1;
            }

            // ---- O += P*V  (V row-major [token][dh] via ldmatrix.trans) ----
            #pragma unroll
            for (int c = 0; c < 4; c++) {
                uint32_t ph[4];
                f162 t0 = __float22half2_rn(make_float2(S[2*c][0],   S[2*c][1]));
                f162 t1 = __float22half2_rn(make_float2(S[2*c][2],   S[2*c][3]));
                f162 t2 = __float22half2_rn(make_float2(S[2*c+1][0], S[2*c+1][1]));
                f162 t3 = __float22half2_rn(make_float2(S[2*c+1][2], S[2*c+1][3]));
                ph[0] = *reinterpret_cast<uint32_t*>(&t0);
                ph[1] = *reinterpret_cast<uint32_t*>(&t1);
                ph[2] = *reinterpret_cast<uint32_t*>(&t2);
                ph[3] = *reinterpret_cast<uint32_t*>(&t3);
                #pragma unroll
                for (int p = 0; p < 4; p++) {
                    // rows = tokens c*16 + {0..15}, cols = dh p*16 + {0..15}
                    uint32_t off = SWZ128((uint32_t)(
                        (c*16 + (g & 1)*8 + lr) * 128 + p*32 + (g >> 1)*16));
                    uint32_t r0, r1, r2, r3;
                    ldsm_x4_trans(vB + off, r0, r1, r2, r3);
                    uint32_t b0[2] = {r0, r1}, b1[2] = {r2, r3};
                    mma_f16(O[p*2],   ph, b0);
                    mma_f16(O[p*2+1], ph, b1);
                }
            }
        }
        __syncthreads();
    }

    // ---- normalize + store att fp16 [B,T,E] ----
    float il0 = 1.0f / l0, il1 = 1.0f / l1;
    #pragma unroll
    for (int j = 0; j < 8; j++) {
        int col = h*64 + j*8 + (lane & 3)*2;
        size_t o_0 = ((size_t)b*TT + trow0) * EE + col;
        size_t o_1 = ((size_t)b*TT + trow1) * EE + col;
        *(f162*)(att + o_0) = __float22half2_rn(
            make_float2(O[j][0]*il0, O[j][1]*il0));
        *(f162*)(att + o_1) = __float22half2_rn(
            make_float2(O[j][2]*il1, O[j][3]*il1));
    }
}

// ============================== launch =====================================
extern "C" void kernel_launch(void* const* d_in, const int* in_sizes, int n_in,
                              void* d_out, int out_size)
{
    const float* x     = (const float*)d_in[0];
    const float* ln1_g = (const float*)d_in[1];
    const float* ln1_b = (const float*)d_in[2];
    const float* Wq    = (const float*)d_in[3];
    const float* Wk    = (const float*)d_in[4];
    const float* Wv    = (const float*)d_in[5];
    const float* Wp    = (const float*)d_in[6];
    const float* bp    = (const float*)d_in[7];
    const float* ln2_g = (const float*)d_in[8];
    const float* ln2_b = (const float*)d_in[9];
    const float* W1    = (const float*)d_in[10];
    const float* b1    = (const float*)d_in[11];
    const float* W2    = (const float*)d_in[12];
    const float* b2    = (const float*)d_in[13];
    float* out = (float*)d_out;

    float *x1;
    f16 *qh_, *kh_, *vh_, *h_, *att_, *ff_;
    f16 *wqT, *WpT, *W1T, *W2T;
    cudaGetSymbolAddress((void**)&x1,  g_x1);
    cudaGetSymbolAddress((void**)&qh_, g_qh);
    cudaGetSymbolAddress((void**)&kh_, g_kh);
    cudaGetSymbolAddress((void**)&vh_, g_vh);
    cudaGetSymbolAddress((void**)&h_,  g_h);
    cudaGetSymbolAddress((void**)&att_, g_att);
    cudaGetSymbolAddress((void**)&ff_, g_ff);
    cudaGetSymbolAddress((void**)&wqT, g_wqkvT);
    cudaGetSymbolAddress((void**)&WpT, g_WpT);
    cudaGetSymbolAddress((void**)&W1T, g_W1T);
    cudaGetSymbolAddress((void**)&W2T, g_W2T);

    cudaFuncSetAttribute(flash_hmma, cudaFuncAttributeMaxDynamicSharedMemorySize, FL_SMEM);
    cudaFuncSetAttribute(gemm_tc<EPI_QKV>,        cudaFuncAttributeMaxDynamicSharedMemorySize, SMEM_GEMM);
    cudaFuncSetAttribute(gemm_tc<EPI_BIAS_RESID>, cudaFuncAttributeMaxDynamicSharedMemorySize, SMEM_GEMM);
    cudaFuncSetAttribute(gemm_tc<EPI_RELU>,       cudaFuncAttributeMaxDynamicSharedMemorySize, SMEM_GEMM);

    // weight prep (fp16, transposed)
    qkvw_kernel<<<dim3(1024/32, 64/32, 48), 256>>>(Wq, Wk, Wv, wqT);
    convt_kernel<<<dim3(1024/32, 1024/32), 256>>>(Wp, WpT, 1024, 1024);
    convt_kernel<<<dim3(4096/32, 1024/32), 256>>>(W1, W1T, 1024, 4096);
    convt_kernel<<<dim3(1024/32, 4096/32), 256>>>(W2, W2T, 4096, 1024);

    // 1. LN1 -> fp16
    ln_kernel<<<MROWS, 256>>>(x, ln1_g, ln1_b, h_);
    // 2. QKV projection -> q (scaled) / k / v fp16
    gemm_tc<EPI_QKV><<<dim3(3072/256, MROWS/128), 256, SMEM_GEMM>>>(
        h_, wqT, 1024, 3072, nullptr, nullptr,
        nullptr, nullptr, qh_, kh_, vh_);
    // 3. flash attention -> att fp16
    flash_hmma<<<dim3(TT/128, BB*HH), 256, FL_SMEM>>>(qh_, kh_, vh_, att_);
    // 4. out-proj + bias + residual -> x1 fp32
    gemm_tc<EPI_BIAS_RESID><<<dim3(1024/256, MROWS/128), 256, SMEM_GEMM>>>(
        att_, WpT, 1024, 1024, bp, x,
        x1, nullptr, nullptr, nullptr, nullptr);
    // 5. LN2 -> fp16
    ln_kernel<<<MROWS, 256>>>(x1, ln2_g, ln2_b, h_);
    // 6. FFN up + relu -> ff fp16
    gemm_tc<EPI_RELU><<<dim3(4096/256, MROWS/128), 256, SMEM_GEMM>>>(
        h_, W1T, 1024, 4096, b1, nullptr,
        nullptr, ff_, nullptr, nullptr, nullptr);
    // 7. FFN down + bias + residual -> out fp32
    gemm_tc<EPI_BIAS_RESID><<<dim3(1024/256, MROWS/128), 256, SMEM_GEMM>>>(
        ff_, W2T, 4096, 1024, b2, x1,
        out, nullptr, nullptr, nullptr, nullptr);
}

// round 7
// speedup vs baseline: 7.7950x; 1.0337x over previous
#include <cuda_runtime.h>
#include <cuda_fp16.h>
#include <cfloat>
#include <cstdint>
#include <math.h>

#define BB 4
#define TT 2048
#define EE 1024
#define HH 16
#define DH 64
#define MROWS (BB*TT)        // 8192

typedef __half  f16;
typedef __half2 f162;

// ============================ scratch =====================================
__device__ float g_x1 [(size_t)MROWS*EE];
__device__ f16  g_qh  [(size_t)BB*HH*TT*DH];
__device__ f16  g_kh  [(size_t)BB*HH*TT*DH];
__device__ f16  g_vh  [(size_t)BB*HH*TT*DH];
__device__ f16  g_h   [(size_t)MROWS*EE];
__device__ f16  g_att [(size_t)MROWS*EE];
__device__ f16  g_ff  [(size_t)MROWS*4096];
__device__ f16  g_wqkvT[(size_t)3072*EE];
__device__ f16  g_WpT[(size_t)EE*EE];
__device__ f16  g_W1T[(size_t)4096*EE];
__device__ f16  g_W2T[(size_t)EE*4096];

// ============================ helpers =====================================
__device__ __forceinline__ uint32_t smem_to_u32(const void* p) {
    uint32_t a;
    asm("{ .reg .u64 t; cvta.to.shared.u64 t, %1; cvt.u32.u64 %0, t; }"
        : "=r"(a) : "l"(p));
    return a;
}

#define SWZ128(o) ((o) ^ (((o) >> 3) & 0x70))

#define CP16(dst, src) \
    asm volatile("cp.async.cg.shared.global [%0], [%1], 16;" \
        :: "r"(dst), "l"(src) : "memory")
#define CP_COMMIT() asm volatile("cp.async.commit_group;" ::: "memory")
#define CP_WAIT(N)  asm volatile("cp.async.wait_group %0;" :: "n"(N) : "memory")

__device__ __forceinline__ void ldsm_x4(uint32_t addr,
    uint32_t& r0, uint32_t& r1, uint32_t& r2, uint32_t& r3) {
    asm volatile("ldmatrix.sync.aligned.m8n8.x4.shared.b16 {%0,%1,%2,%3}, [%4];"
        : "=r"(r0), "=r"(r1), "=r"(r2), "=r"(r3) : "r"(addr));
}
__device__ __forceinline__ void ldsm_x4_trans(uint32_t addr,
    uint32_t& r0, uint32_t& r1, uint32_t& r2, uint32_t& r3) {
    asm volatile("ldmatrix.sync.aligned.m8n8.x4.trans.shared.b16 {%0,%1,%2,%3}, [%4];"
        : "=r"(r0), "=r"(r1), "=r"(r2), "=r"(r3) : "r"(addr));
}

__device__ __forceinline__ void mma_f16(float* c, const uint32_t* a, const uint32_t* b) {
    asm volatile(
        "mma.sync.aligned.m16n8k16.row.col.f32.f16.f16.f32 "
        "{%0,%1,%2,%3}, {%4,%5,%6,%7}, {%8,%9}, {%0,%1,%2,%3};"
        : "+f"(c[0]), "+f"(c[1]), "+f"(c[2]), "+f"(c[3])
        : "r"(a[0]), "r"(a[1]), "r"(a[2]), "r"(a[3]), "r"(b[0]), "r"(b[1]));
}

__device__ __forceinline__ float ex2f(float x) {
    float y;
    asm("ex2.approx.ftz.f32 %0, %1;" : "=f"(y) : "f"(x));
    return y;
}

// ============================ LayerNorm (emits fp16) =======================
__global__ void __launch_bounds__(256) ln_kernel(
    const float* __restrict__ x, const float* __restrict__ g,
    const float* __restrict__ b, f16* __restrict__ oh)
{
    int row = blockIdx.x;
    int tid = threadIdx.x;
    float4 xv = ((const float4*)(x + (size_t)row * EE))[tid];
    float s  = xv.x + xv.y + xv.z + xv.w;
    float s2 = xv.x*xv.x + xv.y*xv.y + xv.z*xv.z + xv.w*xv.w;
    #pragma unroll
    for (int o = 16; o > 0; o >>= 1) {
        s  += __shfl_xor_sync(0xffffffffu, s,  o);
        s2 += __shfl_xor_sync(0xffffffffu, s2, o);
    }
    __shared__ float rs[8], rs2[8];
    int w = tid >> 5;
    if ((tid & 31) == 0) { rs[w] = s; rs2[w] = s2; }
    __syncthreads();
    s = 0.f; s2 = 0.f;
    #pragma unroll
    for (int i = 0; i < 8; i++) { s += rs[i]; s2 += rs2[i]; }
    float mean = s * (1.0f/1024.0f);
    float var  = s2 * (1.0f/1024.0f) - mean*mean;
    float inv  = rsqrtf(var + 1e-5f);
    float4 gv = ((const float4*)g)[tid];
    float4 bv = ((const float4*)b)[tid];
    float o0 = (xv.x - mean)*inv*gv.x + bv.x;
    float o1 = (xv.y - mean)*inv*gv.y + bv.y;
    float o2 = (xv.z - mean)*inv*gv.z + bv.z;
    float o3 = (xv.w - mean)*inv*gv.w + bv.w;
    size_t base = (size_t)row * EE + tid*4;
    *(f162*)(oh+base)   = __float22half2_rn(make_float2(o0,o1));
    *(f162*)(oh+base+2) = __float22half2_rn(make_float2(o2,o3));
}

// ===== fused: Wq/Wk/Wv [H,E,DH] -> wqT fp16 [3*1024 rows, E cols] ==========
__global__ void __launch_bounds__(256) qkvw_kernel(
    const float* __restrict__ Wq, const float* __restrict__ Wk,
    const float* __restrict__ Wv, f16* __restrict__ wqT)
{
    __shared__ float t[32][33];
    int x = threadIdx.x & 31, y = threadIdx.x >> 5;
    int z = blockIdx.z;
    int tq = z >> 4, h = z & 15;
    const float* W = (tq == 0) ? Wq : (tq == 1) ? Wk : Wv;
    int e0 = blockIdx.x * 32, d0 = blockIdx.y * 32;
    #pragma unroll
    for (int i = 0; i < 32; i += 8)
        t[y+i][x] = W[(size_t)h * EE * DH + (size_t)(e0 + y + i) * DH + d0 + x];
    __syncthreads();
    #pragma unroll
    for (int i = 0; i < 32; i += 8) {
        int rown = tq*1024 + h*64 + d0 + y + i;
        wqT[(size_t)rown * EE + e0 + x] = __float2half_rn(t[x][y+i]);
    }
}

// ====== transpose + round: src fp32 [K,N] -> dst fp16 [N,K] ================
__global__ void __launch_bounds__(256) convt_kernel(
    const float* __restrict__ src, f16* __restrict__ dh, int K, int N)
{
    __shared__ float t[32][33];
    int x = threadIdx.x & 31, y = threadIdx.x >> 5;
    int n0 = blockIdx.x * 32, k0 = blockIdx.y * 32;
    #pragma unroll
    for (int i = 0; i < 32; i += 8)
        t[y+i][x] = src[(size_t)(k0 + y + i) * N + n0 + x];
    __syncthreads();
    #pragma unroll
    for (int i = 0; i < 32; i += 8) {
        float vv = t[x][y+i];
        dh[(size_t)(n0 + y + i) * K + k0 + x] = __float2half_rn(vv);
    }
}

// ===== HMMA GEMM: C[M,N] = A[M,K] * B[N,K]^T, fp16, 128x256 tile, 4-stage ==
enum { EPI_QKV = 0, EPI_BIAS_RESID = 1, EPI_RELU = 2 };

#define KCHUNK 64
#define A_TILE_BYTES 16384                // 128 rows x 64 fp16
#define B_TILE_BYTES 32768                // 256 rows x 64 fp16
#define STAGE_BYTES (A_TILE_BYTES + B_TILE_BYTES)   // 49152
#define NSTAGE 4
#define SMEM_GEMM (NSTAGE*STAGE_BYTES + 1024)       // 197632

template<int EPI>
__global__ void __launch_bounds__(256, 1) gemm_tc(
    const f16* __restrict__ A, const f16* __restrict__ B,
    int K, int N,
    const float* __restrict__ bias, const float* __restrict__ resid,
    float* __restrict__ Cf, f16* __restrict__ Of,
    f16* __restrict__ oqh, f16* __restrict__ okh, f16* __restrict__ ovh)
{
    extern __shared__ char smraw[];
    uint32_t raw = smem_to_u32(smraw);
    uint32_t sbase = (raw + 1023u) & ~1023u;

    int tid  = threadIdx.x;
    int wid  = tid >> 5, lane = tid & 31;
    int m0 = blockIdx.y * 128;
    int n0 = blockIdx.x * 256;
    int mw = (wid & 1) * 64;       // warp row offset (2 warps in M)
    int nw = (wid >> 1) * 64;      // warp col offset (4 warps in N)

    const f16* Ap = A + (size_t)m0 * K;
    const f16* Bp = B + (size_t)n0 * K;

    const int nk = K / KCHUNK;     // >= 16 for all our shapes

    auto prefetch = [&](int c) {
        uint32_t st = sbase + (uint32_t)(c % NSTAGE) * STAGE_BYTES;
        int kc = c * KCHUNK;
        #pragma unroll
        for (int it = 0; it < 4; it++) {          // A: 1024 16B units
            int u = tid + it * 256;
            int r = u >> 3, cc = u & 7;
            uint32_t so = st + SWZ128((uint32_t)(r * 128 + cc * 16));
            CP16(so, Ap + (size_t)r * K + kc + cc * 8);
        }
        #pragma unroll
        for (int it = 0; it < 8; it++) {          // B: 2048 16B units
            int u = tid + it * 256;
            int r = u >> 3, cc = u & 7;
            uint32_t so = st + A_TILE_BYTES + SWZ128((uint32_t)(r * 128 + cc * 16));
            CP16(so, Bp + (size_t)r * K + kc + cc * 8);
        }
    };

    float acc[4][8][4];
    #pragma unroll
    for (int mt = 0; mt < 4; mt++)
        #pragma unroll
        for (int nt = 0; nt < 8; nt++)
            #pragma unroll
            for (int q = 0; q < 4; q++) acc[mt][nt][q] = 0.f;

    prefetch(0); CP_COMMIT();
    prefetch(1); CP_COMMIT();
    prefetch(2); CP_COMMIT();

    int g  = lane >> 3;   // ldmatrix lane group
    int lr = lane & 7;

    for (int c = 0; c < nk; c++) {
        CP_WAIT(2);                 // chunk c resident (c+1, c+2 may fly)
        __syncthreads();            // all warps past chunk c-1 reads + visibility
        if (c + 3 < nk) { prefetch(c + 3); CP_COMMIT(); }   // slot (c-1)%4: safe

        uint32_t st = sbase + (uint32_t)(c % NSTAGE) * STAGE_BYTES;
        uint32_t aB = st, bB = st + A_TILE_BYTES;

        #pragma unroll
        for (int ks = 0; ks < 4; ks++) {
            uint32_t ah[4][4], bh[8][2];
            #pragma unroll
            for (int mt = 0; mt < 4; mt++) {
                uint32_t off = SWZ128((uint32_t)(
                    (mw + mt*16 + (g & 1)*8 + lr) * 128 + ks*32 + (g >> 1)*16));
                ldsm_x4(aB + off, ah[mt][0], ah[mt][1], ah[mt][2], ah[mt][3]);
            }
            #pragma unroll
            for (int p = 0; p < 4; p++) {
                uint32_t off = SWZ128((uint32_t)(
                    (nw + p*16 + (g >> 1)*8 + lr) * 128 + ks*32 + (g & 1)*16));
                uint32_t r0, r1, r2, r3;
                ldsm_x4(bB + off, r0, r1, r2, r3);
                bh[p*2][0] = r0; bh[p*2][1] = r1;
                bh[p*2+1][0] = r2; bh[p*2+1][1] = r3;
            }
            #pragma unroll
            for (int mt = 0; mt < 4; mt++)
                #pragma unroll
                for (int nt = 0; nt < 8; nt++)
                    mma_f16(acc[mt][nt], ah[mt], bh[nt]);
        }
    }

    // ------------------------------ epilogue -------------------------------
    int qr = lane >> 2;        // 0..7
    int qc = (lane & 3) * 2;   // 0,2,4,6
    #pragma unroll
    for (int mt = 0; mt < 4; mt++) {
        #pragma unroll
        for (int nt = 0; nt < 8; nt++) {
            int col = n0 + nw + nt*8 + qc;
            #pragma unroll
            for (int half = 0; half < 2; half++) {
                int m = m0 + mw + mt*16 + qr + half*8;
                float v0 = acc[mt][nt][half*2 + 0];
                float v1 = acc[mt][nt][half*2 + 1];
                if (EPI == EPI_QKV) {
                    int bb = m >> 11, tt = m & 2047;
                    int t = col >> 10, nn = col & 1023, h = nn >> 6, d0 = nn & 63;
                    size_t o = (((size_t)(bb*HH + h)) * TT + tt) * DH + d0;
                    // q pre-scaled by E^-0.5 * log2(e) for ex2-softmax
                    float s = (t == 0) ? 0.045084439f : 1.0f;
                    f16* dst = (t == 0) ? oqh : (t == 1) ? okh : ovh;
                    *(f162*)(dst + o) = __float22half2_rn(
                        make_float2(v0 * s, v1 * s));
                } else if (EPI == EPI_BIAS_RESID) {
                    size_t o = (size_t)m * N + col;
                    float2 r2 = *(const float2*)(resid + o);
                    float2 w2;
                    w2.x = v0 + bias[col]     + r2.x;
                    w2.y = v1 + bias[col + 1] + r2.y;
                    *(float2*)(Cf + o) = w2;
                } else { // EPI_RELU
                    size_t o = (size_t)m * N + col;
                    float u0 = fmaxf(v0 + bias[col],     0.f);
                    float u1 = fmaxf(v1 + bias[col + 1], 0.f);
                    *(f162*)(Of + o) = __float22half2_rn(make_float2(u0, u1));
                }
            }
        }
    }
}

// =============== HMMA flash attention: fp16, log2-domain softmax ===========
// smem: Q 16K | stage0 (K 8K, V 8K) | stage1
#define FL_SMEM (16384 + 2*16384)   // 49152

__global__ void __launch_bounds__(256) flash_hmma(
    const f16* __restrict__ qh, const f16* __restrict__ kh,
    const f16* __restrict__ vh, f16* __restrict__ att)
{
    extern __shared__ char smraw[];
    uint32_t sbase = smem_to_u32(smraw);

    int tid  = threadIdx.x;
    int w    = tid >> 5, lane = tid & 31;
    int g    = lane >> 3, lr = lane & 7;
    int qb   = blockIdx.x;          // 0..15
    int bh   = blockIdx.y;          // b*16+h
    int b    = bh >> 4, h = bh & 15;

    const f16* qp = qh + ((size_t)bh * TT + qb*128) * DH;
    const f16* kp = kh + (size_t)bh * TT * DH;
    const f16* vp = vh + (size_t)bh * TT * DH;

    const int ntile = 2*qb + 2;

    // ---- initial copies: Q + stage 0 (one group) ----
    {
        #pragma unroll
        for (int it = 0; it < 4; it++) {
            int u = tid + it * 256;
            int r = u >> 3, cc = u & 7;
            uint32_t so = SWZ128((uint32_t)(r*128 + cc*16));
            CP16(sbase + so, qp + (size_t)r * DH + cc*8);
        }
        #pragma unroll
        for (int it = 0; it < 2; it++) {
            int u = tid + it * 256;     // 512 units: 64 rows x 8
            int r = u >> 3, cc = u & 7;
            uint32_t so = SWZ128((uint32_t)(r*128 + cc*16));
            uint32_t st = sbase + 16384;
            CP16(st + so,        kp + (size_t)r * DH + cc*8);
            CP16(st + 8192 + so, vp + (size_t)r * DH + cc*8);
        }
    }
    CP_COMMIT();

    float O[8][4];
    #pragma unroll
    for (int j = 0; j < 8; j++)
        #pragma unroll
        for (int q = 0; q < 4; q++) O[j][q] = 0.f;
    float m0 = -FLT_MAX, m1 = -FLT_MAX, l0 = 0.f, l1 = 0.f;

    int trow0 = qb*128 + w*16 + (lane >> 2);   // token row of c0/c1
    int trow1 = trow0 + 8;                     // token row of c2/c3
    int rowmaxw = qb*128 + w*16 + 15;

    uint32_t qf[4][4];

    for (int kt = 0; kt < ntile; kt++) {
        CP_WAIT(0);                // tile kt (and Q on kt==0) resident
        __syncthreads();           // all warps done with tile kt-1 + visibility
        if (kt + 1 < ntile) {      // slot (kt+1)&1 == slot of kt-1: safe now
            uint32_t st = sbase + 16384 + (uint32_t)((kt+1) & 1) * 16384;
            const f16* kq = kp + (size_t)(kt+1)*64*DH;
            const f16* vq = vp + (size_t)(kt+1)*64*DH;
            #pragma unroll
            for (int it = 0; it < 2; it++) {
                int u = tid + it * 256;
                int r = u >> 3, cc = u & 7;
                uint32_t so = SWZ128((uint32_t)(r*128 + cc*16));
                CP16(st + so,        kq + (size_t)r * DH + cc*8);
                CP16(st + 8192 + so, vq + (size_t)r * DH + cc*8);
            }
            CP_COMMIT();
        }

        if (kt == 0) {
            #pragma unroll
            for (int c = 0; c < 4; c++) {
                uint32_t off = SWZ128((uint32_t)(
                    (w*16 + (g & 1)*8 + lr) * 128 + c*32 + (g >> 1)*16));
                ldsm_x4(sbase + off, qf[c][0], qf[c][1], qf[c][2], qf[c][3]);
            }
        }

        bool active = (kt*64 <= rowmaxw);
        if (active) {
            uint32_t st = sbase + 16384 + (uint32_t)(kt & 1) * 16384;
            uint32_t kB = st, vB = st + 8192;

            // ---- S = Q*K^T  (log2 domain: q pre-scaled by E^-0.5*log2e) ----
            float S[8][4];
            #pragma unroll
            for (int j = 0; j < 8; j++)
                #pragma unroll
                for (int q = 0; q < 4; q++) S[j][q] = 0.f;
            #pragma unroll
            for (int c = 0; c < 4; c++) {
                #pragma unroll
                for (int p = 0; p < 4; p++) {
                    uint32_t off = SWZ128((uint32_t)(
                        (p*16 + (g >> 1)*8 + lr) * 128 + c*32 + (g & 1)*16));
                    uint32_t r0, r1, r2, r3;
                    ldsm_x4(kB + off, r0, r1, r2, r3);
                    uint32_t b0[2] = {r0, r1}, b1[2] = {r2, r3};
                    mma_f16(S[p*2],   qf[c], b0);
                    mma_f16(S[p*2+1], qf[c], b1);
                }
            }

            // ---- causal mask ----
            if (kt*64 + 63 > trow0) {
                #pragma unroll
                for (int j = 0; j < 8; j++) {
                    int c0 = kt*64 + j*8 + (lane & 3)*2;
                    if (c0     > trow0) S[j][0] = -FLT_MAX;
                    if (c0 + 1 > trow0) S[j][1] = -FLT_MAX;
                    if (c0     > trow1) S[j][2] = -FLT_MAX;
                    if (c0 + 1 > trow1) S[j][3] = -FLT_MAX;
                }
            }

            // ---- online softmax (base-2) ----
            float mx0 = -FLT_MAX, mx1 = -FLT_MAX;
            #pragma unroll
            for (int j = 0; j < 8; j++) {
                mx0 = fmaxf(mx0, fmaxf(S[j][0], S[j][1]));
                mx1 = fmaxf(mx1, fmaxf(S[j][2], S[j][3]));
            }
            mx0 = fmaxf(mx0, __shfl_xor_sync(0xffffffffu, mx0, 1));
            mx0 = fmaxf(mx0, __shfl_xor_sync(0xffffffffu, mx0, 2));
            mx1 = fmaxf(mx1, __shfl_xor_sync(0xffffffffu, mx1, 1));
            mx1 = fmaxf(mx1, __shfl_xor_sync(0xffffffffu, mx1, 2));
            float mn0 = fmaxf(m0, mx0), mn1 = fmaxf(m1, mx1);
            float al0 = ex2f(m0 - mn0), al1 = ex2f(m1 - mn1);
            float rs0 = 0.f, rs1 = 0.f;
            #pragma unroll
            for (int j = 0; j < 8; j++) {
                S[j][0] = ex2f(S[j][0] - mn0);
                S[j][1] = ex2f(S[j][1] - mn0);
                S[j][2] = ex2f(S[j][2] - mn1);
                S[j][3] = ex2f(S[j][3] - mn1);
                rs0 += S[j][0] + S[j][1];
                rs1 += S[j][2] + S[j][3];
            }
            rs0 += __shfl_xor_sync(0xffffffffu, rs0, 1);
            rs0 += __shfl_xor_sync(0xffffffffu, rs0, 2);
            rs1 += __shfl_xor_sync(0xffffffffu, rs1, 1);
            rs1 += __shfl_xor_sync(0xffffffffu, rs1, 2);
            l0 = l0 * al0 + rs0;  m0 = mn0;
            l1 = l1 * al1 + rs1;  m1 = mn1;
            #pragma unroll
            for (int j = 0; j < 8; j++) {
                O[j][0] *= al0; O[j][1] *= al0;
                O[j][2] *= al1; O[j][3] *= al1;
            }

            // ---- O += P*V  (V row-major via ldmatrix.trans) ----
            #pragma unroll
            for (int c = 0; c < 4; c++) {
                uint32_t ph[4];
                f162 t0 = __float22half2_rn(make_float2(S[2*c][0],   S[2*c][1]));
                f162 t1 = __float22half2_rn(make_float2(S[2*c][2],   S[2*c][3]));
                f162 t2 = __float22half2_rn(make_float2(S[2*c+1][0], S[2*c+1][1]));
                f162 t3 = __float22half2_rn(make_float2(S[2*c+1][2], S[2*c+1][3]));
                ph[0] = *reinterpret_cast<uint32_t*>(&t0);
                ph[1] = *reinterpret_cast<uint32_t*>(&t1);
                ph[2] = *reinterpret_cast<uint32_t*>(&t2);
                ph[3] = *reinterpret_cast<uint32_t*>(&t3);
                #pragma unroll
                for (int p = 0; p < 4; p++) {
                    uint32_t off = SWZ128((uint32_t)(
                        (c*16 + (g & 1)*8 + lr) * 128 + p*32 + (g >> 1)*16));
                    uint32_t r0, r1, r2, r3;
                    ldsm_x4_trans(vB + off, r0, r1, r2, r3);
                    uint32_t b0[2] = {r0, r1}, b1[2] = {r2, r3};
                    mma_f16(O[p*2],   ph, b0);
                    mma_f16(O[p*2+1], ph, b1);
                }
            }
        }
    }

    // ---- normalize + store att fp16 [B,T,E] ----
    float il0 = 1.0f / l0, il1 = 1.0f / l1;
    #pragma unroll
    for (int j = 0; j < 8; j++) {
        int col = h*64 + j*8 + (lane & 3)*2;
        size_t o_0 = ((size_t)b*TT + trow0) * EE + col;
        size_t o_1 = ((size_t)b*TT + trow1) * EE + col;
        *(f162*)(att + o_0) = __float22half2_rn(
            make_float2(O[j][0]*il0, O[j][1]*il0));
        *(f162*)(att + o_1) = __float22half2_rn(
            make_float2(O[j][2]*il1, O[j][3]*il1));
    }
}

// ============================== launch =====================================
extern "C" void kernel_launch(void* const* d_in, const int* in_sizes, int n_in,
                              void* d_out, int out_size)
{
    const float* x     = (const float*)d_in[0];
    const float* ln1_g = (const float*)d_in[1];
    const float* ln1_b = (const float*)d_in[2];
    const float* Wq    = (const float*)d_in[3];
    const float* Wk    = (const float*)d_in[4];
    const float* Wv    = (const float*)d_in[5];
    const float* Wp    = (const float*)d_in[6];
    const float* bp    = (const float*)d_in[7];
    const float* ln2_g = (const float*)d_in[8];
    const float* ln2_b = (const float*)d_in[9];
    const float* W1    = (const float*)d_in[10];
    const float* b1    = (const float*)d_in[11];
    const float* W2    = (const float*)d_in[12];
    const float* b2    = (const float*)d_in[13];
    float* out = (float*)d_out;

    float *x1;
    f16 *qh_, *kh_, *vh_, *h_, *att_, *ff_;
    f16 *wqT, *WpT, *W1T, *W2T;
    cudaGetSymbolAddress((void**)&x1,  g_x1);
    cudaGetSymbolAddress((void**)&qh_, g_qh);
    cudaGetSymbolAddress((void**)&kh_, g_kh);
    cudaGetSymbolAddress((void**)&vh_, g_vh);
    cudaGetSymbolAddress((void**)&h_,  g_h);
    cudaGetSymbolAddress((void**)&att_, g_att);
    cudaGetSymbolAddress((void**)&ff_, g_ff);
    cudaGetSymbolAddress((void**)&wqT, g_wqkvT);
    cudaGetSymbolAddress((void**)&WpT, g_WpT);
    cudaGetSymbolAddress((void**)&W1T, g_W1T);
    cudaGetSymbolAddress((void**)&W2T, g_W2T);

    cudaFuncSetAttribute(flash_hmma, cudaFuncAttributeMaxDynamicSharedMemorySize, FL_SMEM);
    cudaFuncSetAttribute(gemm_tc<EPI_QKV>,        cudaFuncAttributeMaxDynamicSharedMemorySize, SMEM_GEMM);
    cudaFuncSetAttribute(gemm_tc<EPI_BIAS_RESID>, cudaFuncAttributeMaxDynamicSharedMemorySize, SMEM_GEMM);
    cudaFuncSetAttribute(gemm_tc<EPI_RELU>,       cudaFuncAttributeMaxDynamicSharedMemorySize, SMEM_GEMM);

    // weight prep (fp16, transposed)
    qkvw_kernel<<<dim3(1024/32, 64/32, 48), 256>>>(Wq, Wk, Wv, wqT);
    convt_kernel<<<dim3(1024/32, 1024/32), 256>>>(Wp, WpT, 1024, 1024);
    convt_kernel<<<dim3(4096/32, 1024/32), 256>>>(W1, W1T, 1024, 4096);
    convt_kernel<<<dim3(1024/32, 4096/32), 256>>>(W2, W2T, 4096, 1024);

    // 1. LN1 -> fp16
    ln_kernel<<<MROWS, 256>>>(x, ln1_g, ln1_b, h_);
    // 2. QKV projection -> q (scaled by E^-0.5*log2e) / k / v fp16
    gemm_tc<EPI_QKV><<<dim3(3072/256, MROWS/128), 256, SMEM_GEMM>>>(
        h_, wqT, 1024, 3072, nullptr, nullptr,
        nullptr, nullptr, qh_, kh_, vh_);
    // 3. flash attention -> att fp16
    flash_hmma<<<dim3(TT/128, BB*HH), 256, FL_SMEM>>>(qh_, kh_, vh_, att_);
    // 4. out-proj + bias + residual -> x1 fp32
    gemm_tc<EPI_BIAS_RESID><<<dim3(1024/256, MROWS/128), 256, SMEM_GEMM>>>(
        att_, WpT, 1024, 1024, bp, x,
        x1, nullptr, nullptr, nullptr, nullptr);
    // 5. LN2 -> fp16
    ln_kernel<<<MROWS, 256>>>(x1, ln2_g, ln2_b, h_);
    // 6. FFN up + relu -> ff fp16
    gemm_tc<EPI_RELU><<<dim3(4096/256, MROWS/128), 256, SMEM_GEMM>>>(
        h_, W1T, 1024, 4096, b1, nullptr,
        nullptr, ff_, nullptr, nullptr, nullptr);
    // 7. FFN down + bias + residual -> out fp32
    gemm_tc<EPI_BIAS_RESID><<<dim3(1024/256, MROWS/128), 256, SMEM_GEMM>>>(
        ff_, W2T, 4096, 1024, b2, x1,
        out, nullptr, nullptr, nullptr, nullptr);
}

// round 8
// speedup vs baseline: 8.0688x; 1.0351x over previous
#include <cuda_runtime.h>
#include <cuda_fp16.h>
#include <cfloat>
#include <cstdint>
#include <math.h>

#define BB 4
#define TT 2048
#define EE 1024
#define HH 16
#define DH 64
#define MROWS (BB*TT)        // 8192

typedef __half  f16;
typedef __half2 f162;

// ============================ scratch =====================================
__device__ float g_x1 [(size_t)MROWS*EE];
__device__ f16  g_qh  [(size_t)BB*HH*TT*DH];
__device__ f16  g_kh  [(size_t)BB*HH*TT*DH];
__device__ f16  g_vh  [(size_t)BB*HH*TT*DH];
__device__ f16  g_h   [(size_t)MROWS*EE];
__device__ f16  g_att [(size_t)MROWS*EE];
__device__ f16  g_ff  [(size_t)MROWS*4096];
__device__ f16  g_wqkvT[(size_t)3072*EE];
__device__ f16  g_WpT[(size_t)EE*EE];
__device__ f16  g_W1T[(size_t)4096*EE];
__device__ f16  g_W2T[(size_t)EE*4096];

// ============================ helpers =====================================
__device__ __forceinline__ uint32_t smem_to_u32(const void* p) {
    uint32_t a;
    asm("{ .reg .u64 t; cvta.to.shared.u64 t, %1; cvt.u32.u64 %0, t; }"
        : "=r"(a) : "l"(p));
    return a;
}

#define SWZ128(o) ((o) ^ (((o) >> 3) & 0x70))

#define CP16(dst, src) \
    asm volatile("cp.async.cg.shared.global [%0], [%1], 16;" \
        :: "r"(dst), "l"(src) : "memory")
#define CP_COMMIT() asm volatile("cp.async.commit_group;" ::: "memory")
#define CP_WAIT(N)  asm volatile("cp.async.wait_group %0;" :: "n"(N) : "memory")

__device__ __forceinline__ void ldsm_x4(uint32_t addr,
    uint32_t& r0, uint32_t& r1, uint32_t& r2, uint32_t& r3) {
    asm volatile("ldmatrix.sync.aligned.m8n8.x4.shared.b16 {%0,%1,%2,%3}, [%4];"
        : "=r"(r0), "=r"(r1), "=r"(r2), "=r"(r3) : "r"(addr));
}
__device__ __forceinline__ void ldsm_x4_trans(uint32_t addr,
    uint32_t& r0, uint32_t& r1, uint32_t& r2, uint32_t& r3) {
    asm volatile("ldmatrix.sync.aligned.m8n8.x4.trans.shared.b16 {%0,%1,%2,%3}, [%4];"
        : "=r"(r0), "=r"(r1), "=r"(r2), "=r"(r3) : "r"(addr));
}

__device__ __forceinline__ void mma_f16(float* c, const uint32_t* a, const uint32_t* b) {
    asm volatile(
        "mma.sync.aligned.m16n8k16.row.col.f32.f16.f16.f32 "
        "{%0,%1,%2,%3}, {%4,%5,%6,%7}, {%8,%9}, {%0,%1,%2,%3};"
        : "+f"(c[0]), "+f"(c[1]), "+f"(c[2]), "+f"(c[3])
        : "r"(a[0]), "r"(a[1]), "r"(a[2]), "r"(a[3]), "r"(b[0]), "r"(b[1]));
}

__device__ __forceinline__ float ex2f(float x) {
    float y;
    asm("ex2.approx.ftz.f32 %0, %1;" : "=f"(y) : "f"(x));
    return y;
}

// ============================ LayerNorm (emits fp16) =======================
__global__ void __launch_bounds__(256) ln_kernel(
    const float* __restrict__ x, const float* __restrict__ g,
    const float* __restrict__ b, f16* __restrict__ oh)
{
    int row = blockIdx.x;
    int tid = threadIdx.x;
    float4 xv = ((const float4*)(x + (size_t)row * EE))[tid];
    float s  = xv.x + xv.y + xv.z + xv.w;
    float s2 = xv.x*xv.x + xv.y*xv.y + xv.z*xv.z + xv.w*xv.w;
    #pragma unroll
    for (int o = 16; o > 0; o >>= 1) {
        s  += __shfl_xor_sync(0xffffffffu, s,  o);
        s2 += __shfl_xor_sync(0xffffffffu, s2, o);
    }
    __shared__ float rs[8], rs2[8];
    int w = tid >> 5;
    if ((tid & 31) == 0) { rs[w] = s; rs2[w] = s2; }
    __syncthreads();
    s = 0.f; s2 = 0.f;
    #pragma unroll
    for (int i = 0; i < 8; i++) { s += rs[i]; s2 += rs2[i]; }
    float mean = s * (1.0f/1024.0f);
    float var  = s2 * (1.0f/1024.0f) - mean*mean;
    float inv  = rsqrtf(var + 1e-5f);
    float4 gv = ((const float4*)g)[tid];
    float4 bv = ((const float4*)b)[tid];
    float o0 = (xv.x - mean)*inv*gv.x + bv.x;
    float o1 = (xv.y - mean)*inv*gv.y + bv.y;
    float o2 = (xv.z - mean)*inv*gv.z + bv.z;
    float o3 = (xv.w - mean)*inv*gv.w + bv.w;
    size_t base = (size_t)row * EE + tid*4;
    *(f162*)(oh+base)   = __float22half2_rn(make_float2(o0,o1));
    *(f162*)(oh+base+2) = __float22half2_rn(make_float2(o2,o3));
}

// ===== fused: Wq/Wk/Wv [H,E,DH] -> wqT fp16 [3*1024 rows, E cols] ==========
__global__ void __launch_bounds__(256) qkvw_kernel(
    const float* __restrict__ Wq, const float* __restrict__ Wk,
    const float* __restrict__ Wv, f16* __restrict__ wqT)
{
    __shared__ float t[32][33];
    int x = threadIdx.x & 31, y = threadIdx.x >> 5;
    int z = blockIdx.z;
    int tq = z >> 4, h = z & 15;
    const float* W = (tq == 0) ? Wq : (tq == 1) ? Wk : Wv;
    int e0 = blockIdx.x * 32, d0 = blockIdx.y * 32;
    #pragma unroll
    for (int i = 0; i < 32; i += 8)
        t[y+i][x] = W[(size_t)h * EE * DH + (size_t)(e0 + y + i) * DH + d0 + x];
    __syncthreads();
    #pragma unroll
    for (int i = 0; i < 32; i += 8) {
        int rown = tq*1024 + h*64 + d0 + y + i;
        wqT[(size_t)rown * EE + e0 + x] = __float2half_rn(t[x][y+i]);
    }
}

// ====== transpose + round: src fp32 [K,N] -> dst fp16 [N,K] ================
__global__ void __launch_bounds__(256) convt_kernel(
    const float* __restrict__ src, f16* __restrict__ dh, int K, int N)
{
    __shared__ float t[32][33];
    int x = threadIdx.x & 31, y = threadIdx.x >> 5;
    int n0 = blockIdx.x * 32, k0 = blockIdx.y * 32;
    #pragma unroll
    for (int i = 0; i < 32; i += 8)
        t[y+i][x] = src[(size_t)(k0 + y + i) * N + n0 + x];
    __syncthreads();
    #pragma unroll
    for (int i = 0; i < 32; i += 8) {
        float vv = t[x][y+i];
        dh[(size_t)(n0 + y + i) * K + k0 + x] = __float2half_rn(vv);
    }
}

// ===== HMMA GEMM: C[M,N] = A[M,K] * B[N,K]^T, fp16, 128x256 tile, 4-stage ==
enum { EPI_QKV = 0, EPI_BIAS_RESID = 1, EPI_RELU = 2 };

#define KCHUNK 64
#define A_TILE_BYTES 16384                // 128 rows x 64 fp16
#define B_TILE_BYTES 32768                // 256 rows x 64 fp16
#define STAGE_BYTES (A_TILE_BYTES + B_TILE_BYTES)   // 49152
#define NSTAGE 4
#define SMEM_GEMM (NSTAGE*STAGE_BYTES + 1024)       // 197632

template<int EPI>
__global__ void __launch_bounds__(256, 1) gemm_tc(
    const f16* __restrict__ A, const f16* __restrict__ B,
    int K, int N,
    const float* __restrict__ bias, const float* __restrict__ resid,
    float* __restrict__ Cf, f16* __restrict__ Of,
    f16* __restrict__ oqh, f16* __restrict__ okh, f16* __restrict__ ovh)
{
    extern __shared__ char smraw[];
    uint32_t raw = smem_to_u32(smraw);
    uint32_t sbase = (raw + 1023u) & ~1023u;

    int tid  = threadIdx.x;
    int wid  = tid >> 5, lane = tid & 31;
    int m0 = blockIdx.y * 128;
    int n0 = blockIdx.x * 256;
    int mw = (wid & 1) * 64;       // warp row offset (2 warps in M)
    int nw = (wid >> 1) * 64;      // warp col offset (4 warps in N)

    const f16* Ap = A + (size_t)m0 * K;
    const f16* Bp = B + (size_t)n0 * K;

    const int nk = K / KCHUNK;     // >= 16 for all our shapes

    auto prefetch = [&](int c) {
        uint32_t st = sbase + (uint32_t)(c % NSTAGE) * STAGE_BYTES;
        int kc = c * KCHUNK;
        #pragma unroll
        for (int it = 0; it < 4; it++) {          // A: 1024 16B units
            int u = tid + it * 256;
            int r = u >> 3, cc = u & 7;
            uint32_t so = st + SWZ128((uint32_t)(r * 128 + cc * 16));
            CP16(so, Ap + (size_t)r * K + kc + cc * 8);
        }
        #pragma unroll
        for (int it = 0; it < 8; it++) {          // B: 2048 16B units
            int u = tid + it * 256;
            int r = u >> 3, cc = u & 7;
            uint32_t so = st + A_TILE_BYTES + SWZ128((uint32_t)(r * 128 + cc * 16));
            CP16(so, Bp + (size_t)r * K + kc + cc * 8);
        }
    };

    float acc[4][8][4];
    #pragma unroll
    for (int mt = 0; mt < 4; mt++)
        #pragma unroll
        for (int nt = 0; nt < 8; nt++)
            #pragma unroll
            for (int q = 0; q < 4; q++) acc[mt][nt][q] = 0.f;

    prefetch(0); CP_COMMIT();
    prefetch(1); CP_COMMIT();
    prefetch(2); CP_COMMIT();

    int g  = lane >> 3;   // ldmatrix lane group
    int lr = lane & 7;

    for (int c = 0; c < nk; c++) {
        CP_WAIT(2);                 // chunk c resident (c+1, c+2 may fly)
        __syncthreads();            // all warps past chunk c-1 reads + visibility
        if (c + 3 < nk) { prefetch(c + 3); CP_COMMIT(); }   // slot (c-1)%4: safe

        uint32_t st = sbase + (uint32_t)(c % NSTAGE) * STAGE_BYTES;
        uint32_t aB = st, bB = st + A_TILE_BYTES;

        #pragma unroll
        for (int ks = 0; ks < 4; ks++) {
            uint32_t ah[4][4], bh[8][2];
            #pragma unroll
            for (int mt = 0; mt < 4; mt++) {
                uint32_t off = SWZ128((uint32_t)(
                    (mw + mt*16 + (g & 1)*8 + lr) * 128 + ks*32 + (g >> 1)*16));
                ldsm_x4(aB + off, ah[mt][0], ah[mt][1], ah[mt][2], ah[mt][3]);
            }
            #pragma unroll
            for (int p = 0; p < 4; p++) {
                uint32_t off = SWZ128((uint32_t)(
                    (nw + p*16 + (g >> 1)*8 + lr) * 128 + ks*32 + (g & 1)*16));
                uint32_t r0, r1, r2, r3;
                ldsm_x4(bB + off, r0, r1, r2, r3);
                bh[p*2][0] = r0; bh[p*2][1] = r1;
                bh[p*2+1][0] = r2; bh[p*2+1][1] = r3;
            }
            #pragma unroll
            for (int mt = 0; mt < 4; mt++)
                #pragma unroll
                for (int nt = 0; nt < 8; nt++)
                    mma_f16(acc[mt][nt], ah[mt], bh[nt]);
        }
    }

    // ------------------------------ epilogue -------------------------------
    int qr = lane >> 2;        // 0..7
    int qc = (lane & 3) * 2;   // 0,2,4,6
    #pragma unroll
    for (int mt = 0; mt < 4; mt++) {
        #pragma unroll
        for (int nt = 0; nt < 8; nt++) {
            int col = n0 + nw + nt*8 + qc;
            #pragma unroll
            for (int half = 0; half < 2; half++) {
                int m = m0 + mw + mt*16 + qr + half*8;
                float v0 = acc[mt][nt][half*2 + 0];
                float v1 = acc[mt][nt][half*2 + 1];
                if (EPI == EPI_QKV) {
                    int bb = m >> 11, tt = m & 2047;
                    int t = col >> 10, nn = col & 1023, h = nn >> 6, d0 = nn & 63;
                    size_t o = (((size_t)(bb*HH + h)) * TT + tt) * DH + d0;
                    // q pre-scaled by E^-0.5 * log2(e) for ex2-softmax
                    float s = (t == 0) ? 0.045084439f : 1.0f;
                    f16* dst = (t == 0) ? oqh : (t == 1) ? okh : ovh;
                    *(f162*)(dst + o) = __float22half2_rn(
                        make_float2(v0 * s, v1 * s));
                } else if (EPI == EPI_BIAS_RESID) {
                    size_t o = (size_t)m * N + col;
                    float2 r2 = *(const float2*)(resid + o);
                    float2 w2;
                    w2.x = v0 + bias[col]     + r2.x;
                    w2.y = v1 + bias[col + 1] + r2.y;
                    *(float2*)(Cf + o) = w2;
                } else { // EPI_RELU
                    size_t o = (size_t)m * N + col;
                    float u0 = fmaxf(v0 + bias[col],     0.f);
                    float u1 = fmaxf(v1 + bias[col + 1], 0.f);
                    *(f162*)(Of + o) = __float22half2_rn(make_float2(u0, u1));
                }
            }
        }
    }
}

// =============== HMMA flash attention: fp16, log2-domain softmax ===========
// grid (bh=64, qbRev=16): heavy q-blocks launch FIRST (LPT scheduling).
// 2 CTAs/SM (regs capped at 128, smem 48K x2 fits).
// smem: Q 16K | stage0 (K 8K, V 8K) | stage1
#define FL_SMEM (16384 + 2*16384)   // 49152

__global__ void __launch_bounds__(256, 2) flash_hmma(
    const f16* __restrict__ qh, const f16* __restrict__ kh,
    const f16* __restrict__ vh, f16* __restrict__ att)
{
    extern __shared__ char smraw[];
    uint32_t sbase = smem_to_u32(smraw);

    int tid  = threadIdx.x;
    int w    = tid >> 5, lane = tid & 31;
    int g    = lane >> 3, lr = lane & 7;
    int qb   = (int)gridDim.y - 1 - (int)blockIdx.y;   // 15..0: heavy first
    int bh   = blockIdx.x;          // b*16+h
    int b    = bh >> 4, h = bh & 15;

    const f16* qp = qh + ((size_t)bh * TT + qb*128) * DH;
    const f16* kp = kh + (size_t)bh * TT * DH;
    const f16* vp = vh + (size_t)bh * TT * DH;

    const int ntile = 2*qb + 2;

    // ---- initial copies: Q + stage 0 (one group) ----
    {
        #pragma unroll
        for (int it = 0; it < 4; it++) {
            int u = tid + it * 256;
            int r = u >> 3, cc = u & 7;
            uint32_t so = SWZ128((uint32_t)(r*128 + cc*16));
            CP16(sbase + so, qp + (size_t)r * DH + cc*8);
        }
        #pragma unroll
        for (int it = 0; it < 2; it++) {
            int u = tid + it * 256;     // 512 units: 64 rows x 8
            int r = u >> 3, cc = u & 7;
            uint32_t so = SWZ128((uint32_t)(r*128 + cc*16));
            uint32_t st = sbase + 16384;
            CP16(st + so,        kp + (size_t)r * DH + cc*8);
            CP16(st + 8192 + so, vp + (size_t)r * DH + cc*8);
        }
    }
    CP_COMMIT();

    float O[8][4];
    #pragma unroll
    for (int j = 0; j < 8; j++)
        #pragma unroll
        for (int q = 0; q < 4; q++) O[j][q] = 0.f;
    float m0 = -FLT_MAX, m1 = -FLT_MAX, l0 = 0.f, l1 = 0.f;

    int trow0 = qb*128 + w*16 + (lane >> 2);   // token row of c0/c1
    int trow1 = trow0 + 8;                     // token row of c2/c3
    int rowmaxw = qb*128 + w*16 + 15;

    uint32_t qf[4][4];

    for (int kt = 0; kt < ntile; kt++) {
        CP_WAIT(0);                // tile kt (and Q on kt==0) resident
        __syncthreads();           // all warps done with tile kt-1 + visibility
        if (kt + 1 < ntile) {      // slot (kt+1)&1 == slot of kt-1: safe now
            uint32_t st = sbase + 16384 + (uint32_t)((kt+1) & 1) * 16384;
            const f16* kq = kp + (size_t)(kt+1)*64*DH;
            const f16* vq = vp + (size_t)(kt+1)*64*DH;
            #pragma unroll
            for (int it = 0; it < 2; it++) {
                int u = tid + it * 256;
                int r = u >> 3, cc = u & 7;
                uint32_t so = SWZ128((uint32_t)(r*128 + cc*16));
                CP16(st + so,        kq + (size_t)r * DH + cc*8);
                CP16(st + 8192 + so, vq + (size_t)r * DH + cc*8);
            }
            CP_COMMIT();
        }

        if (kt == 0) {
            #pragma unroll
            for (int c = 0; c < 4; c++) {
                uint32_t off = SWZ128((uint32_t)(
                    (w*16 + (g & 1)*8 + lr) * 128 + c*32 + (g >> 1)*16));
                ldsm_x4(sbase + off, qf[c][0], qf[c][1], qf[c][2], qf[c][3]);
            }
        }

        bool active = (kt*64 <= rowmaxw);
        if (active) {
            uint32_t st = sbase + 16384 + (uint32_t)(kt & 1) * 16384;
            uint32_t kB = st, vB = st + 8192;

            // ---- S = Q*K^T  (log2 domain: q pre-scaled by E^-0.5*log2e) ----
            float S[8][4];
            #pragma unroll
            for (int j = 0; j < 8; j++)
                #pragma unroll
                for (int q = 0; q < 4; q++) S[j][q] = 0.f;
            #pragma unroll
            for (int c = 0; c < 4; c++) {
                #pragma unroll
                for (int p = 0; p < 4; p++) {
                    uint32_t off = SWZ128((uint32_t)(
                        (p*16 + (g >> 1)*8 + lr) * 128 + c*32 + (g & 1)*16));
                    uint32_t r0, r1, r2, r3;
                    ldsm_x4(kB + off, r0, r1, r2, r3);
                    uint32_t b0[2] = {r0, r1}, b1[2] = {r2, r3};
                    mma_f16(S[p*2],   qf[c], b0);
                    mma_f16(S[p*2+1], qf[c], b1);
                }
            }

            // ---- causal mask ----
            if (kt*64 + 63 > trow0) {
                #pragma unroll
                for (int j = 0; j < 8; j++) {
                    int c0 = kt*64 + j*8 + (lane & 3)*2;
                    if (c0     > trow0) S[j][0] = -FLT_MAX;
                    if (c0 + 1 > trow0) S[j][1] = -FLT_MAX;
                    if (c0     > trow1) S[j][2] = -FLT_MAX;
                    if (c0 + 1 > trow1) S[j][3] = -FLT_MAX;
                }
            }

            // ---- online softmax (base-2) ----
            float mx0 = -FLT_MAX, mx1 = -FLT_MAX;
            #pragma unroll
            for (int j = 0; j < 8; j++) {
                mx0 = fmaxf(mx0, fmaxf(S[j][0], S[j][1]));
                mx1 = fmaxf(mx1, fmaxf(S[j][2], S[j][3]));
            }
            mx0 = fmaxf(mx0, __shfl_xor_sync(0xffffffffu, mx0, 1));
            mx0 = fmaxf(mx0, __shfl_xor_sync(0xffffffffu, mx0, 2));
            mx1 = fmaxf(mx1, __shfl_xor_sync(0xffffffffu, mx1, 1));
            mx1 = fmaxf(mx1, __shfl_xor_sync(0xffffffffu, mx1, 2));
            float mn0 = fmaxf(m0, mx0), mn1 = fmaxf(m1, mx1);
            float al0 = ex2f(m0 - mn0), al1 = ex2f(m1 - mn1);
            float rs0 = 0.f, rs1 = 0.f;
            #pragma unroll
            for (int j = 0; j < 8; j++) {
                S[j][0] = ex2f(S[j][0] - mn0);
                S[j][1] = ex2f(S[j][1] - mn0);
                S[j][2] = ex2f(S[j][2] - mn1);
                S[j][3] = ex2f(S[j][3] - mn1);
                rs0 += S[j][0] + S[j][1];
                rs1 += S[j][2] + S[j][3];
            }
            rs0 += __shfl_xor_sync(0xffffffffu, rs0, 1);
            rs0 += __shfl_xor_sync(0xffffffffu, rs0, 2);
            rs1 += __shfl_xor_sync(0xffffffffu, rs1, 1);
            rs1 += __shfl_xor_sync(0xffffffffu, rs1, 2);
            l0 = l0 * al0 + rs0;  m0 = mn0;
            l1 = l1 * al1 + rs1;  m1 = mn1;
            #pragma unroll
            for (int j = 0; j < 8; j++) {
                O[j][0] *= al0; O[j][1] *= al0;
                O[j][2] *= al1; O[j][3] *= al1;
            }

            // ---- O += P*V  (V row-major via ldmatrix.trans) ----
            #pragma unroll
            for (int c = 0; c < 4; c++) {
                uint32_t ph[4];
                f162 t0 = __float22half2_rn(make_float2(S[2*c][0],   S[2*c][1]));
                f162 t1 = __float22half2_rn(make_float2(S[2*c][2],   S[2*c][3]));
                f162 t2 = __float22half2_rn(make_float2(S[2*c+1][0], S[2*c+1][1]));
                f162 t3 = __float22half2_rn(make_float2(S[2*c+1][2], S[2*c+1][3]));
                ph[0] = *reinterpret_cast<uint32_t*>(&t0);
                ph[1] = *reinterpret_cast<uint32_t*>(&t1);
                ph[2] = *reinterpret_cast<uint32_t*>(&t2);
                ph[3] = *reinterpret_cast<uint32_t*>(&t3);
                #pragma unroll
                for (int p = 0; p < 4; p++) {
                    uint32_t off = SWZ128((uint32_t)(
                        (c*16 + (g & 1)*8 + lr) * 128 + p*32 + (g >> 1)*16));
                    uint32_t r0, r1, r2, r3;
                    ldsm_x4_trans(vB + off, r0, r1, r2, r3);
                    uint32_t b0[2] = {r0, r1}, b1[2] = {r2, r3};
                    mma_f16(O[p*2],   ph, b0);
                    mma_f16(O[p*2+1], ph, b1);
                }
            }
        }
    }

    // ---- normalize + store att fp16 [B,T,E] ----
    float il0 = 1.0f / l0, il1 = 1.0f / l1;
    #pragma unroll
    for (int j = 0; j < 8; j++) {
        int col = h*64 + j*8 + (lane & 3)*2;
        size_t o_0 = ((size_t)b*TT + trow0) * EE + col;
        size_t o_1 = ((size_t)b*TT + trow1) * EE + col;
        *(f162*)(att + o_0) = __float22half2_rn(
            make_float2(O[j][0]*il0, O[j][1]*il0));
        *(f162*)(att + o_1) = __float22half2_rn(
            make_float2(O[j][2]*il1, O[j][3]*il1));
    }
}

// ============================== launch =====================================
extern "C" void kernel_launch(void* const* d_in, const int* in_sizes, int n_in,
                              void* d_out, int out_size)
{
    const float* x     = (const float*)d_in[0];
    const float* ln1_g = (const float*)d_in[1];
    const float* ln1_b = (const float*)d_in[2];
    const float* Wq    = (const float*)d_in[3];
    const float* Wk    = (const float*)d_in[4];
    const float* Wv    = (const float*)d_in[5];
    const float* Wp    = (const float*)d_in[6];
    const float* bp    = (const float*)d_in[7];
    const float* ln2_g = (const float*)d_in[8];
    const float* ln2_b = (const float*)d_in[9];
    const float* W1    = (const float*)d_in[10];
    const float* b1    = (const float*)d_in[11];
    const float* W2    = (const float*)d_in[12];
    const float* b2    = (const float*)d_in[13];
    float* out = (float*)d_out;

    float *x1;
    f16 *qh_, *kh_, *vh_, *h_, *att_, *ff_;
    f16 *wqT, *WpT, *W1T, *W2T;
    cudaGetSymbolAddress((void**)&x1,  g_x1);
    cudaGetSymbolAddress((void**)&qh_, g_qh);
    cudaGetSymbolAddress((void**)&kh_, g_kh);
    cudaGetSymbolAddress((void**)&vh_, g_vh);
    cudaGetSymbolAddress((void**)&h_,  g_h);
    cudaGetSymbolAddress((void**)&att_, g_att);
    cudaGetSymbolAddress((void**)&ff_, g_ff);
    cudaGetSymbolAddress((void**)&wqT, g_wqkvT);
    cudaGetSymbolAddress((void**)&WpT, g_WpT);
    cudaGetSymbolAddress((void**)&W1T, g_W1T);
    cudaGetSymbolAddress((void**)&W2T, g_W2T);

    cudaFuncSetAttribute(flash_hmma, cudaFuncAttributeMaxDynamicSharedMemorySize, FL_SMEM);
    cudaFuncSetAttribute(gemm_tc<EPI_QKV>,        cudaFuncAttributeMaxDynamicSharedMemorySize, SMEM_GEMM);
    cudaFuncSetAttribute(gemm_tc<EPI_BIAS_RESID>, cudaFuncAttributeMaxDynamicSharedMemorySize, SMEM_GEMM);
    cudaFuncSetAttribute(gemm_tc<EPI_RELU>,       cudaFuncAttributeMaxDynamicSharedMemorySize, SMEM_GEMM);

    // weight prep (fp16, transposed)
    qkvw_kernel<<<dim3(1024/32, 64/32, 48), 256>>>(Wq, Wk, Wv, wqT);
    convt_kernel<<<dim3(1024/32, 1024/32), 256>>>(Wp, WpT, 1024, 1024);
    convt_kernel<<<dim3(4096/32, 1024/32), 256>>>(W1, W1T, 1024, 4096);
    convt_kernel<<<dim3(1024/32, 4096/32), 256>>>(W2, W2T, 4096, 1024);

    // 1. LN1 -> fp16
    ln_kernel<<<MROWS, 256>>>(x, ln1_g, ln1_b, h_);
    // 2. QKV projection -> q (scaled by E^-0.5*log2e) / k / v fp16
    gemm_tc<EPI_QKV><<<dim3(3072/256, MROWS/128), 256, SMEM_GEMM>>>(
        h_, wqT, 1024, 3072, nullptr, nullptr,
        nullptr, nullptr, qh_, kh_, vh_);
    // 3. flash attention -> att fp16 (LPT: heavy q-blocks first)
    flash_hmma<<<dim3(BB*HH, TT/128), 256, FL_SMEM>>>(qh_, kh_, vh_, att_);
    // 4. out-proj + bias + residual -> x1 fp32
    gemm_tc<EPI_BIAS_RESID><<<dim3(1024/256, MROWS/128), 256, SMEM_GEMM>>>(
        att_, WpT, 1024, 1024, bp, x,
        x1, nullptr, nullptr, nullptr, nullptr);
    // 5. LN2 -> fp16
    ln_kernel<<<MROWS, 256>>>(x1, ln2_g, ln2_b, h_);
    // 6. FFN up + relu -> ff fp16
    gemm_tc<EPI_RELU><<<dim3(4096/256, MROWS/128), 256, SMEM_GEMM>>>(
        h_, W1T, 1024, 4096, b1, nullptr,
        nullptr, ff_, nullptr, nullptr, nullptr);
    // 7. FFN down + bias + residual -> out fp32
    gemm_tc<EPI_BIAS_RESID><<<dim3(1024/256, MROWS/128), 256, SMEM_GEMM>>>(
        ff_, W2T, 4096, 1024, b2, x1,
        out, nullptr, nullptr, nullptr, nullptr);
}